// round 13
// baseline (speedup 1.0000x reference)
#include <cuda_runtime.h>
#include <cuda_fp16.h>
#include <cstdint>

#define NNODES 10000
#define NEDGES 320000
#define CH     256

// ---- scratch (static device allocations; no cudaMalloc allowed) ----
__device__ __align__(16) __half g_xhi[NNODES * 64];
__device__ __align__(16) __half g_xlo[NNODES * 64];
__device__ __align__(16) __half g_Hhi[NNODES * CH];
__device__ __align__(16) __half g_Ahi[NNODES * CH];   // relu(agg) split, next-layer input
__device__ __align__(16) __half g_Alo[NNODES * CH];
__device__ __align__(16) __half g_AB [NNODES * 2 * CH];
__device__ __align__(16) __half g_Wlhi[3][CH * CH];       // W_lin fp16 (layer0: 256x64)
__device__ __align__(16) __half g_WlThi[3][CH * CH];      // W_lin^T fp16 (rows k_in, cols m)
__device__ __align__(16) __half g_Wshi[3][2 * CH * CH];   // W_s1 uniform [512,256] split
__device__ __align__(16) __half g_Wslo[3][2 * CH * CH];
__device__ __align__(16) __half g_Wchi[3][2 * CH * CH];   // Wc = Ws @ Wlin  [512, K_l] fp16
__device__ float g_b768[3][768];                          // [b_lin | Ws@b_lin + b_s1pad]
__device__ int g_rowptr[NNODES + 1];
__device__ int g_cnt[NNODES];   // starts 0; hist fills; scatter's atomicSub restores to 0
__device__ int g_col[NEDGES];

__device__ __forceinline__ uint32_t sptr(const void* p) {
    return (uint32_t)__cvta_generic_to_shared(p);
}
__device__ __forceinline__ void cpa16(uint32_t dst, const void* src, bool pred) {
    int sz = pred ? 16 : 0;
    asm volatile("cp.async.cg.shared.global [%0], [%1], 16, %2;"
                 :: "r"(dst), "l"(src), "r"(sz));
}
__device__ __forceinline__ void cpa_commit() {
    asm volatile("cp.async.commit_group;" ::: "memory");
}

// ============================================================================
// ONE fused prep kernel: x split, Wlin fp16, Wlin^T fp16, Ws uniform split,
// fused bias b768, AND the dst histogram (g_cnt starts at 0 — restored by
// scatter's atomicSub on the previous launch/replay).
// ============================================================================
#define CX    (NNODES * 64)
#define S_WL0 (CX)
#define S_WL1 (S_WL0 + 16384)
#define S_WL2 (S_WL1 + 65536)
#define S_WT0 (S_WL2 + 65536)
#define S_WT1 (S_WT0 + 16384)
#define S_WT2 (S_WT1 + 65536)
#define S_WS0 (S_WT2 + 65536)
#define S_WS1 (S_WS0 + 131072)
#define S_WS2 (S_WS1 + 131072)
#define S_BIA (S_WS2 + 131072)
#define S_HST (S_BIA + 3 * 768)
#define S_END (S_HST + NEDGES)

__global__ void __launch_bounds__(256) cvt_all(
    const float* __restrict__ x, const int* __restrict__ ei,
    const float* __restrict__ Wl1, const float* __restrict__ Wl2, const float* __restrict__ Wl3,
    const float* __restrict__ Ws1, const float* __restrict__ Ws2, const float* __restrict__ Ws3,
    const float* __restrict__ bl1, const float* __restrict__ bl2, const float* __restrict__ bl3,
    const float* __restrict__ bs1, const float* __restrict__ bs2, const float* __restrict__ bs3)
{
    int i = blockIdx.x * blockDim.x + threadIdx.x;
    if (i >= S_END) return;
    if (i < CX) {
        float v = x[i];
        __half h = __float2half_rn(v);
        g_xhi[i] = h;
        g_xlo[i] = __float2half_rn(v - __half2float(h));
        return;
    }
    if (i < S_WT0) {   // Wlin fp16 copy
        int l, j; const float* W;
        if (i < S_WL1)      { l = 0; j = i - S_WL0; W = Wl1; }
        else if (i < S_WL2) { l = 1; j = i - S_WL1; W = Wl2; }
        else                { l = 2; j = i - S_WL2; W = Wl3; }
        g_Wlhi[l][j] = __float2half_rn(W[j]);
        return;
    }
    if (i < S_WS0) {   // Wlin^T fp16: [k_in][m] from Wlin[m*kin + k]
        int l, j, kin; const float* W;
        if (i < S_WT1)      { l = 0; j = i - S_WT0; W = Wl1; kin = 64; }
        else if (i < S_WT2) { l = 1; j = i - S_WT1; W = Wl2; kin = 256; }
        else                { l = 2; j = i - S_WT2; W = Wl3; kin = 256; }
        int k = j >> 8, m = j & 255;
        g_WlThi[l][j] = __float2half_rn(W[m * kin + k]);
        return;
    }
    if (i < S_BIA) {   // Ws uniform repack + hi/lo split
        int l, j; const float* W;
        if (i < S_WS1)      { l = 0; j = i - S_WS0; W = Ws1; }
        else if (i < S_WS2) { l = 1; j = i - S_WS1; W = Ws2; }
        else                { l = 2; j = i - S_WS2; W = Ws3; }
        int r = j >> 8, k = j & 255;
        float v = (r < CH) ? W[r * 2 * CH + k] : W[(r - CH) * 2 * CH + CH + k];
        __half h = __float2half_rn(v);
        g_Wshi[l][j] = h;
        g_Wslo[l][j] = __float2half_rn(v - __half2float(h));
        return;
    }
    if (i < S_HST) {   // fused bias: b768[l] = [b_lin | Ws@b_lin + b_s1pad]
        int q = i - S_BIA;
        int l = q / 768, j = q % 768;
        const float* bl = (l == 0) ? bl1 : (l == 1) ? bl2 : bl3;
        const float* Ws = (l == 0) ? Ws1 : (l == 1) ? Ws2 : Ws3;
        const float* bs = (l == 0) ? bs1 : (l == 1) ? bs2 : bs3;
        if (j < 256) { g_b768[l][j] = bl[j]; return; }
        int r = j - 256;
        float acc = (r < CH) ? bs[r] : 0.f;
        for (int m = 0; m < 256; m++) {
            float w = (r < CH) ? Ws[r * 2 * CH + m] : Ws[(r - CH) * 2 * CH + CH + m];
            acc += w * bl[m];
        }
        g_b768[l][j] = acc;
        return;
    }
    // dst histogram
    atomicAdd(&g_cnt[ei[NEDGES + (i - S_HST)]], 1);
}

// ============================================================================
// Single-pass scan: 1024 threads x 10 elements, 2 barriers total.
// Does NOT modify g_cnt (scatter restores it to zero).
// ============================================================================
__global__ void __launch_bounds__(1024) scan_kernel() {
    __shared__ int wsum[32];
    const int t = threadIdx.x, lane = t & 31, w = t >> 5;
    const int base_i = t * 10;
    int v[10];
    int s = 0;
    #pragma unroll
    for (int q = 0; q < 10; q++) {
        int idx = base_i + q;
        v[q] = (idx < NNODES) ? g_cnt[idx] : 0;
        s += v[q];
    }
    int x = s;
    #pragma unroll
    for (int o = 1; o < 32; o <<= 1) {
        int y = __shfl_up_sync(0xffffffffu, x, o);
        if (lane >= o) x += y;
    }
    if (lane == 31) wsum[w] = x;
    __syncthreads();
    if (w == 0) {
        int z = wsum[lane];
        #pragma unroll
        for (int o = 1; o < 32; o <<= 1) {
            int y = __shfl_up_sync(0xffffffffu, z, o);
            if (lane >= o) z += y;
        }
        wsum[lane] = z;
    }
    __syncthreads();
    int run = (x - s) + (w > 0 ? wsum[w - 1] : 0);   // exclusive prefix for this thread
    #pragma unroll
    for (int q = 0; q < 10; q++) {
        int idx = base_i + q;
        if (idx < NNODES) g_rowptr[idx] = run;
        run += v[q];
    }
    if (t == 1023) g_rowptr[NNODES] = wsum[31];
}

// scatter restores g_cnt to all-zero (atomicSub), keeping replays deterministic.
__global__ void scatter_kernel(const int* __restrict__ ei) {
    int e = blockIdx.x * blockDim.x + threadIdx.x;
    if (e < NEDGES) {
        int s = ei[e];
        int d = ei[NEDGES + e];
        int old = atomicSub(&g_cnt[d], 1);
        g_col[g_rowptr[d] + old - 1] = s;
    }
}

// ============================================================================
// GEMM core: 2-region split (A = hi+lo exact vs fp16 W; W fp16 single).
// Virtual K' = 2K over regions: (Ahi,W), (Alo,W).
// BM=128 BN=64 BK=32, 8 warps, warp tile 32x32 (4M x 2N),
// 3-stage cp.async pipeline with ONE __syncthreads per chunk:
//   wait_group(1) -> sync -> issue(ch+2) -> compute(ch)
// (issue targets buf (ch+2)%3, last used by chunk ch-1, finished before sync).
// 64B smem rows swizzled (cq ^ ((row>>1)&3)) -> conflict-free ldmatrix.
// DUALW: weight rows n<256 from Wa, n>=256 from Wb (both stride K).
// OUTMODE 1: dual single-fp16 out (n<256 -> out0 stride 256, else out1 stride 512), +bias.
// OUTMODE 2: single fp16 out0 stride ostride, no bias.
// ============================================================================
template<int OUTMODE, bool DUALW>
__device__ __forceinline__ void gemm_core(
    const __half* __restrict__ Ahi, const __half* __restrict__ Alo,
    const __half* __restrict__ Wahi, const __half* __restrict__ Wbhi,
    const float* __restrict__ bias,
    __half* __restrict__ out0, __half* __restrict__ out1,
    int M, int K, int ostride, int bm, int bn)
{
    constexpr int BM = 128, BN = 64, BK = 32, ST = 3;
    __shared__ __align__(16) __half sA[ST][BM * BK];   // 24 KB
    __shared__ __align__(16) __half sB[ST][BN * BK];   // 12 KB  (36 KB total)

    const int tid  = threadIdx.x;
    const int lane = tid & 31;
    const int warp = tid >> 5;
    const int wm   = (warp >> 1) * 32;
    const int wn   = (warp & 1) * 32;
    const int nch  = (2 * K) / BK;

    const bool useB = DUALW && (bn >= 256);
    const int  nb   = useB ? bn - 256 : bn;
    const __half* Whi = useB ? Wbhi : Wahi;

    float c[2][4][4];
    #pragma unroll
    for (int i = 0; i < 2; i++)
        #pragma unroll
        for (int j = 0; j < 4; j++)
            #pragma unroll
            for (int q = 0; q < 4; q++) c[i][j][q] = 0.f;

    auto issue = [&](int ch) {
        int buf = ch % ST;
        int k0v = ch * BK;
        int region = k0v / K;
        int kreal  = k0v - region * K;
        const __half* As = (region == 1) ? Alo : Ahi;
        uint32_t baseA = sptr(&sA[buf][0]);
        uint32_t baseB = sptr(&sB[buf][0]);
        // A tile: 128 rows x 64B = 512 x 16B chunks, 2 per thread
        #pragma unroll
        for (int p = 0; p < 2; p++) {
            int idx = tid + p * 256;
            int row = idx >> 2;
            int cq  = idx & 3;
            int gm  = bm + row;
            bool ok = gm < M;
            const __half* src = As + (size_t)(ok ? gm : 0) * K + kreal + cq * 8;
            cpa16(baseA + row * 64 + ((cq ^ ((row >> 1) & 3)) << 4), src, ok);
        }
        // W tile: 64 rows x 64B = 256 x 16B chunks, 1 per thread
        {
            int row = tid >> 2;
            int cq  = tid & 3;
            const __half* src = Whi + (size_t)(nb + row) * K + kreal + cq * 8;
            cpa16(baseB + row * 64 + ((cq ^ ((row >> 1) & 3)) << 4), src, true);
        }
        cpa_commit();
    };

    auto compute = [&](int buf) {
        uint32_t baseA = sptr(&sA[buf][0]);
        uint32_t baseB = sptr(&sB[buf][0]);
        #pragma unroll
        for (int kk = 0; kk < 2; kk++) {
            int cl = kk * 2 + (lane >> 4);
            uint32_t bf[2][4];
            #pragma unroll
            for (int h = 0; h < 2; h++) {
                int row = wn + h * 16 + (lane & 15);
                uint32_t p = baseB + row * 64 + ((cl ^ ((row >> 1) & 3)) << 4);
                asm volatile("ldmatrix.sync.aligned.m8n8.x4.shared.b16 {%0,%1,%2,%3}, [%4];"
                             : "=r"(bf[h][0]), "=r"(bf[h][1]), "=r"(bf[h][2]), "=r"(bf[h][3]) : "r"(p));
            }
            #pragma unroll
            for (int fi = 0; fi < 2; fi++) {
                uint32_t a0, a1, a2, a3;
                int row = wm + fi * 16 + (lane & 15);
                uint32_t p = baseA + row * 64 + ((cl ^ ((row >> 1) & 3)) << 4);
                asm volatile("ldmatrix.sync.aligned.m8n8.x4.shared.b16 {%0,%1,%2,%3}, [%4];"
                             : "=r"(a0), "=r"(a1), "=r"(a2), "=r"(a3) : "r"(p));
                #pragma unroll
                for (int h = 0; h < 2; h++) {
                    asm volatile("mma.sync.aligned.m16n8k16.row.col.f32.f16.f16.f32 "
                                 "{%0,%1,%2,%3}, {%4,%5,%6,%7}, {%8,%9}, {%0,%1,%2,%3};"
                                 : "+f"(c[fi][2*h+0][0]), "+f"(c[fi][2*h+0][1]), "+f"(c[fi][2*h+0][2]), "+f"(c[fi][2*h+0][3])
                                 : "r"(a0), "r"(a1), "r"(a2), "r"(a3), "r"(bf[h][0]), "r"(bf[h][2]));
                    asm volatile("mma.sync.aligned.m16n8k16.row.col.f32.f16.f16.f32 "
                                 "{%0,%1,%2,%3}, {%4,%5,%6,%7}, {%8,%9}, {%0,%1,%2,%3};"
                                 : "+f"(c[fi][2*h+1][0]), "+f"(c[fi][2*h+1][1]), "+f"(c[fi][2*h+1][2]), "+f"(c[fi][2*h+1][3])
                                 : "r"(a0), "r"(a1), "r"(a2), "r"(a3), "r"(bf[h][1]), "r"(bf[h][3]));
                }
            }
        }
    };

    issue(0);
    if (nch > 1) issue(1);
    for (int ch = 0; ch < nch; ch++) {
        if (ch + 1 < nch) asm volatile("cp.async.wait_group 1;" ::: "memory");
        else              asm volatile("cp.async.wait_group 0;" ::: "memory");
        __syncthreads();
        if (ch + 2 < nch) issue(ch + 2);
        compute(ch % ST);
    }

    // ---- epilogue ----
    __half* dst;
    int stride, cb;
    if (OUTMODE == 1) {
        dst    = useB ? out1 : out0;
        stride = useB ? 512 : 256;
        cb     = nb;
    } else {
        dst    = out0;
        stride = ostride;
        cb     = bn;
    }
    #pragma unroll
    for (int fi = 0; fi < 2; fi++) {
        int row0 = bm + wm + fi * 16 + (lane >> 2);
        #pragma unroll
        for (int nj = 0; nj < 4; nj++) {
            int cl = wn + nj * 8 + (lane & 3) * 2;
            float bx = 0.f, by = 0.f;
            if (OUTMODE == 1) { bx = bias[bn + cl]; by = bias[bn + cl + 1]; }
            float v0 = c[fi][nj][0] + bx, v1 = c[fi][nj][1] + by;
            float v2 = c[fi][nj][2] + bx, v3 = c[fi][nj][3] + by;
            int col = cb + cl;
            if (row0 < M)
                *reinterpret_cast<__half2*>(&dst[(size_t)row0 * stride + col]) = __floats2half2_rn(v0, v1);
            if (row0 + 8 < M)
                *reinterpret_cast<__half2*>(&dst[(size_t)(row0 + 8) * stride + col]) = __floats2half2_rn(v2, v3);
        }
    }
}

// Wc precompute, layer 0 only: Wc[0] = Ws[0](split) @ WlT[0] -> fp16 [512, 64]
__global__ void __launch_bounds__(256) wc_gemm0() {
    gemm_core<2, false>(g_Wshi[0], g_Wslo[0], g_WlThi[0], nullptr,
                        nullptr, g_Wchi[0], nullptr, 512, 256, 64,
                        blockIdx.x * 128, 0);
}

// Wc precompute, layers 1-2 (runs on side stream, overlapped with agg1)
__global__ void __launch_bounds__(256) wc_gemm12() {
    int l = blockIdx.z + 1;
    gemm_core<2, false>(g_Wshi[l], g_Wslo[l], g_WlThi[l], nullptr,
                        nullptr, g_Wchi[l], nullptr, 512, 256, 256,
                        blockIdx.x * 128, blockIdx.y * 64);
}

// Fused per-layer GEMM: [Hhi | AB] = relu_in @ [Wlin ; Wc]^T + b768
__global__ void __launch_bounds__(256) layer_gemm(
    const __half* __restrict__ Ahi, const __half* __restrict__ Alo,
    int l, int K, __half* __restrict__ Hhi, __half* __restrict__ AB)
{
    gemm_core<1, true>(Ahi, Alo, g_Wlhi[l], g_Wchi[l],
                       g_b768[l], Hhi, AB, NNODES, K, 0,
                       blockIdx.x * 128, blockIdx.y * 64);
}

// ============================================================================
// Fused score + aggregate: one warp per dst node (CSR), no atomics.
// 2-edge ILP. MODE 0: relu-split hi/lo fp16 out. MODE 1: fp32 out (final).
// ============================================================================
template<int MODE>
__global__ void __launch_bounds__(256) agg_kernel(
    const __half* __restrict__ AB,
    const __half* __restrict__ Hhi,
    const float* __restrict__ w2, const float* __restrict__ b2,
    float* __restrict__ outf, __half* __restrict__ ohi, __half* __restrict__ olo)
{
    const int lane = threadIdx.x & 31;
    const int d    = blockIdx.x * (blockDim.x >> 5) + (threadIdx.x >> 5);
    if (d >= NNODES) return;

    const float4 w0 = *reinterpret_cast<const float4*>(&w2[lane * 8]);
    const float4 w1 = *reinterpret_cast<const float4*>(&w2[lane * 8 + 4]);
    const float  bb = b2[0];

    uint4 araw = *reinterpret_cast<const uint4*>(&AB[(size_t)d * (2 * CH) + lane * 8]);
    float2 a0 = __half22float2(*reinterpret_cast<__half2*>(&araw.x));
    float2 a1 = __half22float2(*reinterpret_cast<__half2*>(&araw.y));
    float2 a2 = __half22float2(*reinterpret_cast<__half2*>(&araw.z));
    float2 a3 = __half22float2(*reinterpret_cast<__half2*>(&araw.w));

    float acc0 = 0.f, acc1 = 0.f, acc2 = 0.f, acc3 = 0.f;
    float acc4 = 0.f, acc5 = 0.f, acc6 = 0.f, acc7 = 0.f;

    auto partial = [&](int s, uint4& hraw) -> float {
        uint4 braw = *reinterpret_cast<const uint4*>(&AB[(size_t)s * (2 * CH) + CH + lane * 8]);
        hraw = *reinterpret_cast<const uint4*>(&Hhi[(size_t)s * CH + lane * 8]);
        float2 b0 = __half22float2(*reinterpret_cast<__half2*>(&braw.x));
        float2 b1 = __half22float2(*reinterpret_cast<__half2*>(&braw.y));
        float2 b2v = __half22float2(*reinterpret_cast<__half2*>(&braw.z));
        float2 b3 = __half22float2(*reinterpret_cast<__half2*>(&braw.w));
        float p;
        p  = fmaxf(a0.x + b0.x, 0.f) * w0.x;
        p += fmaxf(a0.y + b0.y, 0.f) * w0.y;
        p += fmaxf(a1.x + b1.x, 0.f) * w0.z;
        p += fmaxf(a1.y + b1.y, 0.f) * w0.w;
        p += fmaxf(a2.x + b2v.x, 0.f) * w1.x;
        p += fmaxf(a2.y + b2v.y, 0.f) * w1.y;
        p += fmaxf(a3.x + b3.x, 0.f) * w1.z;
        p += fmaxf(a3.y + b3.y, 0.f) * w1.w;
        return p;
    };

    auto accum = [&](float score, const uint4& hraw) {
        float2 h0 = __half22float2(*reinterpret_cast<const __half2*>(&hraw.x));
        float2 h1 = __half22float2(*reinterpret_cast<const __half2*>(&hraw.y));
        float2 h2 = __half22float2(*reinterpret_cast<const __half2*>(&hraw.z));
        float2 h3 = __half22float2(*reinterpret_cast<const __half2*>(&hraw.w));
        acc0 = fmaf(score, h0.x, acc0);
        acc1 = fmaf(score, h0.y, acc1);
        acc2 = fmaf(score, h1.x, acc2);
        acc3 = fmaf(score, h1.y, acc3);
        acc4 = fmaf(score, h2.x, acc4);
        acc5 = fmaf(score, h2.y, acc5);
        acc6 = fmaf(score, h3.x, acc6);
        acc7 = fmaf(score, h3.y, acc7);
    };

    const int beg = g_rowptr[d];
    const int end = g_rowptr[d + 1];

    // self-loop first
    {
        uint4 hraw;
        float p = partial(d, hraw);
        #pragma unroll
        for (int off = 16; off > 0; off >>= 1)
            p += __shfl_xor_sync(0xffffffffu, p, off);
        accum(1.f / (1.f + __expf(-(p + bb))), hraw);
    }

    int i = beg;
    for (; i + 1 < end; i += 2) {
        int s0 = g_col[i];
        int s1 = g_col[i + 1];
        uint4 hraw0, hraw1;
        float p0 = partial(s0, hraw0);
        float p1 = partial(s1, hraw1);
        #pragma unroll
        for (int off = 16; off > 0; off >>= 1) {
            p0 += __shfl_xor_sync(0xffffffffu, p0, off);
            p1 += __shfl_xor_sync(0xffffffffu, p1, off);
        }
        float sc0 = 1.f / (1.f + __expf(-(p0 + bb)));
        float sc1 = 1.f / (1.f + __expf(-(p1 + bb)));
        accum(sc0, hraw0);
        accum(sc1, hraw1);
    }
    if (i < end) {
        uint4 hraw;
        float p = partial(g_col[i], hraw);
        #pragma unroll
        for (int off = 16; off > 0; off >>= 1)
            p += __shfl_xor_sync(0xffffffffu, p, off);
        accum(1.f / (1.f + __expf(-(p + bb))), hraw);
    }

    if (MODE == 1) {
        float* op = &outf[(size_t)d * CH + lane * 8];
        *reinterpret_cast<float4*>(op)     = make_float4(acc0, acc1, acc2, acc3);
        *reinterpret_cast<float4*>(op + 4) = make_float4(acc4, acc5, acc6, acc7);
    } else {
        float r[8] = {fmaxf(acc0, 0.f), fmaxf(acc1, 0.f), fmaxf(acc2, 0.f), fmaxf(acc3, 0.f),
                      fmaxf(acc4, 0.f), fmaxf(acc5, 0.f), fmaxf(acc6, 0.f), fmaxf(acc7, 0.f)};
        __half h[8], l[8];
        #pragma unroll
        for (int q = 0; q < 8; q++) {
            h[q] = __float2half_rn(r[q]);
            l[q] = __float2half_rn(r[q] - __half2float(h[q]));
        }
        uint4 hv, lv;
        hv.x = *reinterpret_cast<unsigned*>(&__halves2half2(h[0], h[1]));
        hv.y = *reinterpret_cast<unsigned*>(&__halves2half2(h[2], h[3]));
        hv.z = *reinterpret_cast<unsigned*>(&__halves2half2(h[4], h[5]));
        hv.w = *reinterpret_cast<unsigned*>(&__halves2half2(h[6], h[7]));
        lv.x = *reinterpret_cast<unsigned*>(&__halves2half2(l[0], l[1]));
        lv.y = *reinterpret_cast<unsigned*>(&__halves2half2(l[2], l[3]));
        lv.z = *reinterpret_cast<unsigned*>(&__halves2half2(l[4], l[5]));
        lv.w = *reinterpret_cast<unsigned*>(&__halves2half2(l[6], l[7]));
        *reinterpret_cast<uint4*>(&ohi[(size_t)d * CH + lane * 8]) = hv;
        *reinterpret_cast<uint4*>(&olo[(size_t)d * CH + lane * 8]) = lv;
    }
}

extern "C" void kernel_launch(void* const* d_in, const int* in_sizes, int n_in,
                              void* d_out, int out_size)
{
    (void)in_sizes; (void)n_in; (void)out_size;
    const float* x  = (const float*)d_in[0];
    const int*   ei = (const int*)d_in[1];
    const float* W_lin[3] = {(const float*)d_in[2],  (const float*)d_in[8],  (const float*)d_in[14]};
    const float* b_lin[3] = {(const float*)d_in[3],  (const float*)d_in[9],  (const float*)d_in[15]};
    const float* W_s1[3]  = {(const float*)d_in[4],  (const float*)d_in[10], (const float*)d_in[16]};
    const float* b_s1[3]  = {(const float*)d_in[5],  (const float*)d_in[11], (const float*)d_in[17]};
    const float* W_s2[3]  = {(const float*)d_in[6],  (const float*)d_in[12], (const float*)d_in[18]};
    const float* b_s2[3]  = {(const float*)d_in[7],  (const float*)d_in[13], (const float*)d_in[19]};

    __half *xhi, *xlo, *Hhi, *Ahi, *Alo, *AB;
    cudaGetSymbolAddress((void**)&xhi, g_xhi);
    cudaGetSymbolAddress((void**)&xlo, g_xlo);
    cudaGetSymbolAddress((void**)&Hhi, g_Hhi);
    cudaGetSymbolAddress((void**)&Ahi, g_Ahi);
    cudaGetSymbolAddress((void**)&Alo, g_Alo);
    cudaGetSymbolAddress((void**)&AB,  g_AB);
    float* out = (float*)d_out;

    const dim3 blk(256);
    const dim3 gL((NNODES + 127) / 128, 768 / 64);   // (79, 12)
    const dim3 gWc12(4, 4, 2);
    const int  agrid = (NNODES + 7) / 8;

    // Fork/join resources (host-side objects only; replays execute the graph).
    cudaStream_t side;
    cudaEvent_t  evFork, evJoin1, evJoin2;
    cudaStreamCreateWithFlags(&side, cudaStreamNonBlocking);
    cudaEventCreateWithFlags(&evFork,  cudaEventDisableTiming);
    cudaEventCreateWithFlags(&evJoin1, cudaEventDisableTiming);
    cudaEventCreateWithFlags(&evJoin2, cudaEventDisableTiming);

    // ---- one-shot prep (conversions + bias + dst histogram) ----
    cvt_all<<<(S_END + 255) / 256, blk>>>(x, ei, W_lin[0], W_lin[1], W_lin[2],
                                          W_s1[0], W_s1[1], W_s1[2],
                                          b_lin[0], b_lin[1], b_lin[2],
                                          b_s1[0], b_s1[1], b_s1[2]);

    // ---- fork ----
    cudaEventRecord(evFork, 0);
    cudaStreamWaitEvent(side, evFork, 0);

    // side stream: CSR finish, then Wc for layers 1-2 (overlaps agg1)
    scan_kernel<<<1, 1024, 0, side>>>();
    scatter_kernel<<<(NEDGES + 255) / 256, blk, 0, side>>>(ei);
    cudaEventRecord(evJoin1, side);
    wc_gemm12<<<gWc12, blk, 0, side>>>();
    cudaEventRecord(evJoin2, side);

    // main stream: Wc[0] (tiny) + layer-1 GEMM
    wc_gemm0<<<4, blk>>>();
    layer_gemm<<<gL, blk>>>(xhi, xlo, 0, 64, Hhi, AB);

    // join 1: agg1 needs g_col/g_rowptr
    cudaStreamWaitEvent(0, evJoin1, 0);
    agg_kernel<0><<<agrid, blk>>>(AB, Hhi, W_s2[0], b_s2[0], nullptr, Ahi, Alo);

    // join 2: layer 2 needs Wc[1] (and later Wc[2])
    cudaStreamWaitEvent(0, evJoin2, 0);
    layer_gemm<<<gL, blk>>>(Ahi, Alo, 1, 256, Hhi, AB);
    agg_kernel<0><<<agrid, blk>>>(AB, Hhi, W_s2[1], b_s2[1], nullptr, Ahi, Alo);

    // ---- layer 3 (writes d_out) ----
    layer_gemm<<<gL, blk>>>(Ahi, Alo, 2, 256, Hhi, AB);
    agg_kernel<1><<<agrid, blk>>>(AB, Hhi, W_s2[2], b_s2[2], out, nullptr, nullptr);
}

// round 15
// speedup vs baseline: 1.0277x; 1.0277x over previous
#include <cuda_runtime.h>
#include <cuda_fp16.h>
#include <cstdint>

#define NNODES 10000
#define NEDGES 320000
#define CH     256

// ---- scratch (static device allocations; no cudaMalloc allowed) ----
__device__ __align__(16) __half g_xhi[NNODES * 64];
__device__ __align__(16) __half g_xlo[NNODES * 64];
__device__ __align__(16) __half g_Hhi[NNODES * CH];
__device__ __align__(16) __half g_Ahi[NNODES * CH];   // relu(agg) split, next-layer input
__device__ __align__(16) __half g_Alo[NNODES * CH];
__device__ __align__(16) __half g_AB [NNODES * 2 * CH];
__device__ __align__(16) __half g_Wlhi[3][CH * CH];       // W_lin fp16 (layer0: 256x64)
__device__ __align__(16) __half g_WlThi[3][CH * CH];      // W_lin^T fp16 (rows k_in, cols m)
__device__ __align__(16) __half g_Wshi[3][2 * CH * CH];   // W_s1 uniform [512,256] split
__device__ __align__(16) __half g_Wslo[3][2 * CH * CH];
__device__ __align__(16) __half g_Wchi[3][2 * CH * CH];   // Wc = Ws @ Wlin  [512, K_l] fp16
__device__ float g_b768[3][768];                          // [b_lin | Ws@b_lin + b_s1pad]
__device__ int g_rowptr[NNODES + 1];
__device__ int g_cnt[NNODES];   // starts 0; hist fills; scatter's atomicSub restores to 0
__device__ int g_col[NEDGES];

__device__ __forceinline__ uint32_t sptr(const void* p) {
    return (uint32_t)__cvta_generic_to_shared(p);
}
__device__ __forceinline__ void cpa16(uint32_t dst, const void* src, bool pred) {
    int sz = pred ? 16 : 0;
    asm volatile("cp.async.cg.shared.global [%0], [%1], 16, %2;"
                 :: "r"(dst), "l"(src), "r"(sz));
}
__device__ __forceinline__ void cpa_commit() {
    asm volatile("cp.async.commit_group;" ::: "memory");
}

__device__ __forceinline__ void split4(float4 v, uint2& hi, uint2& lo) {
    __half h0 = __float2half_rn(v.x), h1 = __float2half_rn(v.y);
    __half h2 = __float2half_rn(v.z), h3 = __float2half_rn(v.w);
    __half l0 = __float2half_rn(v.x - __half2float(h0));
    __half l1 = __float2half_rn(v.y - __half2float(h1));
    __half l2 = __float2half_rn(v.z - __half2float(h2));
    __half l3 = __float2half_rn(v.w - __half2float(h3));
    __half2 ph0 = __halves2half2(h0, h1), ph1 = __halves2half2(h2, h3);
    __half2 pl0 = __halves2half2(l0, l1), pl1 = __halves2half2(l2, l3);
    hi.x = *reinterpret_cast<unsigned*>(&ph0); hi.y = *reinterpret_cast<unsigned*>(&ph1);
    lo.x = *reinterpret_cast<unsigned*>(&pl0); lo.y = *reinterpret_cast<unsigned*>(&pl1);
}

// ============================================================================
// Fused prep kernel (vectorized), FIXED segment chain:
//   [0, E_X4)        : x hi/lo split, float4 (160000)
//   [E_X4, E_WL)     : Wlin fp16 copy, float4 (36864)
//   [E_WL, E_WT)     : Wlin^T fp16 scalar gather (147456)
//   [E_WT, E_WS)     : Ws uniform repack + hi/lo split, float4 (98304)
//   [E_WS, E_BI)     : fused bias (2304)
// Histogram/scan/scatter run concurrently on the side stream (disjoint outputs).
// ============================================================================
#define E_X4  (NNODES * 64 / 4)
#define E_WL  (E_X4 + 147456 / 4)
#define E_WT  (E_WL + 147456)
#define E_WS  (E_WT + 393216 / 4)
#define E_BI  (E_WS + 3 * 768)

__global__ void __launch_bounds__(256) cvt_all(
    const float* __restrict__ x,
    const float* __restrict__ Wl1, const float* __restrict__ Wl2, const float* __restrict__ Wl3,
    const float* __restrict__ Ws1, const float* __restrict__ Ws2, const float* __restrict__ Ws3,
    const float* __restrict__ bl1, const float* __restrict__ bl2, const float* __restrict__ bl3,
    const float* __restrict__ bs1, const float* __restrict__ bs2, const float* __restrict__ bs3)
{
    int i = blockIdx.x * blockDim.x + threadIdx.x;
    if (i >= E_BI) return;
    if (i < E_X4) {                       // x hi/lo split, 4 elems
        float4 v = reinterpret_cast<const float4*>(x)[i];
        uint2 hi, lo;
        split4(v, hi, lo);
        reinterpret_cast<uint2*>(g_xhi)[i] = hi;
        reinterpret_cast<uint2*>(g_xlo)[i] = lo;
        return;
    }
    if (i < E_WL) {                       // Wlin fp16 copy, 4 elems
        int q = i - E_X4;                 // 0..36863 (layer bounds: 4096, 20480)
        int l, u; const float* W;
        if (q < 4096)        { l = 0; u = q;         W = Wl1; }
        else if (q < 20480)  { l = 1; u = q - 4096;  W = Wl2; }
        else                 { l = 2; u = q - 20480; W = Wl3; }
        float4 v = reinterpret_cast<const float4*>(W)[u];
        __half2 p0 = __floats2half2_rn(v.x, v.y);
        __half2 p1 = __floats2half2_rn(v.z, v.w);
        uint2 pk;
        pk.x = *reinterpret_cast<unsigned*>(&p0);
        pk.y = *reinterpret_cast<unsigned*>(&p1);
        reinterpret_cast<uint2*>(g_Wlhi[l])[u] = pk;
        return;
    }
    if (i < E_WT) {                       // Wlin^T fp16 scalar gather
        int q = i - E_WL;                 // 0..147455 (bounds: 16384, 81920)
        int l, j, kin; const float* W;
        if (q < 16384)       { l = 0; j = q;         W = Wl1; kin = 64; }
        else if (q < 81920)  { l = 1; j = q - 16384; W = Wl2; kin = 256; }
        else                 { l = 2; j = q - 81920; W = Wl3; kin = 256; }
        int k = j >> 8, m = j & 255;
        g_WlThi[l][j] = __float2half_rn(W[m * kin + k]);
        return;
    }
    if (i < E_WS) {                       // Ws uniform repack + hi/lo split, 4 elems
        int q = i - E_WT;                 // 0..98303, 32768 per layer
        int l = q >> 15, u = q & 32767;
        const float* W = (l == 0) ? Ws1 : (l == 1) ? Ws2 : Ws3;
        int j = u * 4;                    // element index in uniform [512,256]
        int r = j >> 8, k = j & 255;      // k..k+3 within one row (k%4==0, never crosses)
        const float* src = (r < CH) ? (W + r * 2 * CH + k)
                                    : (W + (r - CH) * 2 * CH + CH + k);
        float4 v = *reinterpret_cast<const float4*>(src);
        uint2 hi, lo;
        split4(v, hi, lo);
        reinterpret_cast<uint2*>(g_Wshi[l])[u] = hi;
        reinterpret_cast<uint2*>(g_Wslo[l])[u] = lo;
        return;
    }
    {                                     // fused bias
        int q = i - E_WS;
        int l = q / 768, j = q % 768;
        const float* bl = (l == 0) ? bl1 : (l == 1) ? bl2 : bl3;
        const float* Ws = (l == 0) ? Ws1 : (l == 1) ? Ws2 : Ws3;
        const float* bs = (l == 0) ? bs1 : (l == 1) ? bs2 : bs3;
        if (j < 256) { g_b768[l][j] = bl[j]; return; }
        int r = j - 256;
        float acc = (r < CH) ? bs[r] : 0.f;
        for (int m = 0; m < 256; m++) {
            float w = (r < CH) ? Ws[r * 2 * CH + m] : Ws[(r - CH) * 2 * CH + CH + m];
            acc += w * bl[m];
        }
        g_b768[l][j] = acc;
    }
}

__global__ void __launch_bounds__(256) hist_kernel(const int* __restrict__ ei) {
    int e = blockIdx.x * blockDim.x + threadIdx.x;
    if (e < NEDGES) atomicAdd(&g_cnt[ei[NEDGES + e]], 1);
}

// ============================================================================
// Single-pass scan: 1024 threads x 10 elements, 2 barriers total.
// Does NOT modify g_cnt (scatter restores it to zero).
// ============================================================================
__global__ void __launch_bounds__(1024) scan_kernel() {
    __shared__ int wsum[32];
    const int t = threadIdx.x, lane = t & 31, w = t >> 5;
    const int base_i = t * 10;
    int v[10];
    int s = 0;
    #pragma unroll
    for (int q = 0; q < 10; q++) {
        int idx = base_i + q;
        v[q] = (idx < NNODES) ? g_cnt[idx] : 0;
        s += v[q];
    }
    int x = s;
    #pragma unroll
    for (int o = 1; o < 32; o <<= 1) {
        int y = __shfl_up_sync(0xffffffffu, x, o);
        if (lane >= o) x += y;
    }
    if (lane == 31) wsum[w] = x;
    __syncthreads();
    if (w == 0) {
        int z = wsum[lane];
        #pragma unroll
        for (int o = 1; o < 32; o <<= 1) {
            int y = __shfl_up_sync(0xffffffffu, z, o);
            if (lane >= o) z += y;
        }
        wsum[lane] = z;
    }
    __syncthreads();
    int run = (x - s) + (w > 0 ? wsum[w - 1] : 0);
    #pragma unroll
    for (int q = 0; q < 10; q++) {
        int idx = base_i + q;
        if (idx < NNODES) g_rowptr[idx] = run;
        run += v[q];
    }
    if (t == 1023) g_rowptr[NNODES] = wsum[31];
}

// scatter restores g_cnt to all-zero (atomicSub), keeping replays deterministic.
__global__ void scatter_kernel(const int* __restrict__ ei) {
    int e = blockIdx.x * blockDim.x + threadIdx.x;
    if (e < NEDGES) {
        int s = ei[e];
        int d = ei[NEDGES + e];
        int old = atomicSub(&g_cnt[d], 1);
        g_col[g_rowptr[d] + old - 1] = s;
    }
}

// ============================================================================
// GEMM core (R12 config — frozen): 2-region split, BM=128 BN=64 BK=64,
// 8 warps, warp tile 32x32, 2-stage cp.async, 128B-row XOR swizzle.
// ============================================================================
template<int OUTMODE, bool DUALW>
__device__ __forceinline__ void gemm_core(
    const __half* __restrict__ Ahi, const __half* __restrict__ Alo,
    const __half* __restrict__ Wahi, const __half* __restrict__ Wbhi,
    const float* __restrict__ bias,
    __half* __restrict__ out0, __half* __restrict__ out1,
    int M, int K, int ostride, int bm, int bn)
{
    constexpr int BM = 128, BN = 64, BK = 64;
    __shared__ __align__(16) __half sA[2][BM * BK];   // 32 KB
    __shared__ __align__(16) __half sB[2][BN * BK];   // 16 KB

    const int tid  = threadIdx.x;
    const int lane = tid & 31;
    const int warp = tid >> 5;
    const int wm   = (warp >> 1) * 32;
    const int wn   = (warp & 1) * 32;
    const int nch  = (2 * K) / BK;

    const int chunk = tid & 7;
    const int rbase = tid >> 3;

    const bool useB = DUALW && (bn >= 256);
    const int  nb   = useB ? bn - 256 : bn;
    const __half* Whi = useB ? Wbhi : Wahi;

    float c[2][4][4];
    #pragma unroll
    for (int i = 0; i < 2; i++)
        #pragma unroll
        for (int j = 0; j < 4; j++)
            #pragma unroll
            for (int q = 0; q < 4; q++) c[i][j][q] = 0.f;

    auto issue = [&](int ch) {
        int buf = ch & 1;
        int k0v = ch * BK;
        int region = k0v / K;
        int kreal  = k0v - region * K;
        const __half* As = (region == 1) ? Alo : Ahi;
        uint32_t baseA = sptr(&sA[buf][0]);
        uint32_t baseB = sptr(&sB[buf][0]);
        #pragma unroll
        for (int i = 0; i < 4; i++) {
            int row = rbase + 32 * i;
            int gm  = bm + row;
            bool ok = gm < M;
            const __half* src = As + (size_t)(ok ? gm : 0) * K + kreal + chunk * 8;
            cpa16(baseA + row * 128 + ((chunk ^ (row & 7)) << 4), src, ok);
        }
        #pragma unroll
        for (int i = 0; i < 2; i++) {
            int row = rbase + 32 * i;
            const __half* src = Whi + (size_t)(nb + row) * K + kreal + chunk * 8;
            cpa16(baseB + row * 128 + ((chunk ^ (row & 7)) << 4), src, true);
        }
        cpa_commit();
    };

    auto compute = [&](int buf) {
        uint32_t baseA = sptr(&sA[buf][0]);
        uint32_t baseB = sptr(&sB[buf][0]);
        #pragma unroll
        for (int kk = 0; kk < 4; kk++) {
            int cl = kk * 2 + (lane >> 4);
            uint32_t bf[2][4];
            #pragma unroll
            for (int h = 0; h < 2; h++) {
                int row = wn + h * 16 + (lane & 15);
                uint32_t p = baseB + row * 128 + ((cl ^ (row & 7)) << 4);
                asm volatile("ldmatrix.sync.aligned.m8n8.x4.shared.b16 {%0,%1,%2,%3}, [%4];"
                             : "=r"(bf[h][0]), "=r"(bf[h][1]), "=r"(bf[h][2]), "=r"(bf[h][3]) : "r"(p));
            }
            #pragma unroll
            for (int fi = 0; fi < 2; fi++) {
                uint32_t a0, a1, a2, a3;
                int row = wm + fi * 16 + (lane & 15);
                uint32_t p = baseA + row * 128 + ((cl ^ (row & 7)) << 4);
                asm volatile("ldmatrix.sync.aligned.m8n8.x4.shared.b16 {%0,%1,%2,%3}, [%4];"
                             : "=r"(a0), "=r"(a1), "=r"(a2), "=r"(a3) : "r"(p));
                #pragma unroll
                for (int h = 0; h < 2; h++) {
                    asm volatile("mma.sync.aligned.m16n8k16.row.col.f32.f16.f16.f32 "
                                 "{%0,%1,%2,%3}, {%4,%5,%6,%7}, {%8,%9}, {%0,%1,%2,%3};"
                                 : "+f"(c[fi][2*h+0][0]), "+f"(c[fi][2*h+0][1]), "+f"(c[fi][2*h+0][2]), "+f"(c[fi][2*h+0][3])
                                 : "r"(a0), "r"(a1), "r"(a2), "r"(a3), "r"(bf[h][0]), "r"(bf[h][2]));
                    asm volatile("mma.sync.aligned.m16n8k16.row.col.f32.f16.f16.f32 "
                                 "{%0,%1,%2,%3}, {%4,%5,%6,%7}, {%8,%9}, {%0,%1,%2,%3};"
                                 : "+f"(c[fi][2*h+1][0]), "+f"(c[fi][2*h+1][1]), "+f"(c[fi][2*h+1][2]), "+f"(c[fi][2*h+1][3])
                                 : "r"(a0), "r"(a1), "r"(a2), "r"(a3), "r"(bf[h][1]), "r"(bf[h][3]));
                }
            }
        }
    };

    issue(0);
    if (nch > 1) issue(1);
    for (int ch = 0; ch < nch; ch++) {
        if (ch + 1 < nch) asm volatile("cp.async.wait_group 1;" ::: "memory");
        else              asm volatile("cp.async.wait_group 0;" ::: "memory");
        __syncthreads();
        compute(ch & 1);
        __syncthreads();
        if (ch + 2 < nch) issue(ch + 2);
    }

    // ---- epilogue ----
    __half* dst;
    int stride, cb;
    if (OUTMODE == 1) {
        dst    = useB ? out1 : out0;
        stride = useB ? 512 : 256;
        cb     = nb;
    } else {
        dst    = out0;
        stride = ostride;
        cb     = bn;
    }
    #pragma unroll
    for (int fi = 0; fi < 2; fi++) {
        int row0 = bm + wm + fi * 16 + (lane >> 2);
        #pragma unroll
        for (int nj = 0; nj < 4; nj++) {
            int cl = wn + nj * 8 + (lane & 3) * 2;
            float bx = 0.f, by = 0.f;
            if (OUTMODE == 1) { bx = bias[bn + cl]; by = bias[bn + cl + 1]; }
            float v0 = c[fi][nj][0] + bx, v1 = c[fi][nj][1] + by;
            float v2 = c[fi][nj][2] + bx, v3 = c[fi][nj][3] + by;
            int col = cb + cl;
            if (row0 < M)
                *reinterpret_cast<__half2*>(&dst[(size_t)row0 * stride + col]) = __floats2half2_rn(v0, v1);
            if (row0 + 8 < M)
                *reinterpret_cast<__half2*>(&dst[(size_t)(row0 + 8) * stride + col]) = __floats2half2_rn(v2, v3);
        }
    }
}

// Wc precompute, layer 0 only: Wc[0] = Ws[0](split) @ WlT[0] -> fp16 [512, 64]
__global__ void __launch_bounds__(256) wc_gemm0() {
    gemm_core<2, false>(g_Wshi[0], g_Wslo[0], g_WlThi[0], nullptr,
                        nullptr, g_Wchi[0], nullptr, 512, 256, 64,
                        blockIdx.x * 128, 0);
}

// Wc precompute, layers 1-2 (side stream, overlapped with agg1)
__global__ void __launch_bounds__(256) wc_gemm12() {
    int l = blockIdx.z + 1;
    gemm_core<2, false>(g_Wshi[l], g_Wslo[l], g_WlThi[l], nullptr,
                        nullptr, g_Wchi[l], nullptr, 512, 256, 256,
                        blockIdx.x * 128, blockIdx.y * 64);
}

// Fused per-layer GEMM: [Hhi | AB] = relu_in @ [Wlin ; Wc]^T + b768
__global__ void __launch_bounds__(256) layer_gemm(
    const __half* __restrict__ Ahi, const __half* __restrict__ Alo,
    int l, int K, __half* __restrict__ Hhi, __half* __restrict__ AB)
{
    gemm_core<1, true>(Ahi, Alo, g_Wlhi[l], g_Wchi[l],
                       g_b768[l], Hhi, AB, NNODES, K, 0,
                       blockIdx.x * 128, blockIdx.y * 64);
}

// ============================================================================
// Fused score + aggregate: one warp per dst node (CSR), no atomics.
// 2-edge ILP. MODE 0: relu-split hi/lo fp16 out. MODE 1: fp32 out (final).
// ============================================================================
template<int MODE>
__global__ void __launch_bounds__(256) agg_kernel(
    const __half* __restrict__ AB,
    const __half* __restrict__ Hhi,
    const float* __restrict__ w2, const float* __restrict__ b2,
    float* __restrict__ outf, __half* __restrict__ ohi, __half* __restrict__ olo)
{
    const int lane = threadIdx.x & 31;
    const int d    = blockIdx.x * (blockDim.x >> 5) + (threadIdx.x >> 5);
    if (d >= NNODES) return;

    const float4 w0 = *reinterpret_cast<const float4*>(&w2[lane * 8]);
    const float4 w1 = *reinterpret_cast<const float4*>(&w2[lane * 8 + 4]);
    const float  bb = b2[0];

    uint4 araw = *reinterpret_cast<const uint4*>(&AB[(size_t)d * (2 * CH) + lane * 8]);
    float2 a0 = __half22float2(*reinterpret_cast<__half2*>(&araw.x));
    float2 a1 = __half22float2(*reinterpret_cast<__half2*>(&araw.y));
    float2 a2 = __half22float2(*reinterpret_cast<__half2*>(&araw.z));
    float2 a3 = __half22float2(*reinterpret_cast<__half2*>(&araw.w));

    float acc0 = 0.f, acc1 = 0.f, acc2 = 0.f, acc3 = 0.f;
    float acc4 = 0.f, acc5 = 0.f, acc6 = 0.f, acc7 = 0.f;

    auto partial = [&](int s, uint4& hraw) -> float {
        uint4 braw = *reinterpret_cast<const uint4*>(&AB[(size_t)s * (2 * CH) + CH + lane * 8]);
        hraw = *reinterpret_cast<const uint4*>(&Hhi[(size_t)s * CH + lane * 8]);
        float2 b0 = __half22float2(*reinterpret_cast<__half2*>(&braw.x));
        float2 b1 = __half22float2(*reinterpret_cast<__half2*>(&braw.y));
        float2 b2v = __half22float2(*reinterpret_cast<__half2*>(&braw.z));
        float2 b3 = __half22float2(*reinterpret_cast<__half2*>(&braw.w));
        float p;
        p  = fmaxf(a0.x + b0.x, 0.f) * w0.x;
        p += fmaxf(a0.y + b0.y, 0.f) * w0.y;
        p += fmaxf(a1.x + b1.x, 0.f) * w0.z;
        p += fmaxf(a1.y + b1.y, 0.f) * w0.w;
        p += fmaxf(a2.x + b2v.x, 0.f) * w1.x;
        p += fmaxf(a2.y + b2v.y, 0.f) * w1.y;
        p += fmaxf(a3.x + b3.x, 0.f) * w1.z;
        p += fmaxf(a3.y + b3.y, 0.f) * w1.w;
        return p;
    };

    auto accum = [&](float score, const uint4& hraw) {
        float2 h0 = __half22float2(*reinterpret_cast<const __half2*>(&hraw.x));
        float2 h1 = __half22float2(*reinterpret_cast<const __half2*>(&hraw.y));
        float2 h2 = __half22float2(*reinterpret_cast<const __half2*>(&hraw.z));
        float2 h3 = __half22float2(*reinterpret_cast<const __half2*>(&hraw.w));
        acc0 = fmaf(score, h0.x, acc0);
        acc1 = fmaf(score, h0.y, acc1);
        acc2 = fmaf(score, h1.x, acc2);
        acc3 = fmaf(score, h1.y, acc3);
        acc4 = fmaf(score, h2.x, acc4);
        acc5 = fmaf(score, h2.y, acc5);
        acc6 = fmaf(score, h3.x, acc6);
        acc7 = fmaf(score, h3.y, acc7);
    };

    const int beg = g_rowptr[d];
    const int end = g_rowptr[d + 1];

    // self-loop first
    {
        uint4 hraw;
        float p = partial(d, hraw);
        #pragma unroll
        for (int off = 16; off > 0; off >>= 1)
            p += __shfl_xor_sync(0xffffffffu, p, off);
        accum(1.f / (1.f + __expf(-(p + bb))), hraw);
    }

    int i = beg;
    for (; i + 1 < end; i += 2) {
        int s0 = g_col[i];
        int s1 = g_col[i + 1];
        uint4 hraw0, hraw1;
        float p0 = partial(s0, hraw0);
        float p1 = partial(s1, hraw1);
        #pragma unroll
        for (int off = 16; off > 0; off >>= 1) {
            p0 += __shfl_xor_sync(0xffffffffu, p0, off);
            p1 += __shfl_xor_sync(0xffffffffu, p1, off);
        }
        float sc0 = 1.f / (1.f + __expf(-(p0 + bb)));
        float sc1 = 1.f / (1.f + __expf(-(p1 + bb)));
        accum(sc0, hraw0);
        accum(sc1, hraw1);
    }
    if (i < end) {
        uint4 hraw;
        float p = partial(g_col[i], hraw);
        #pragma unroll
        for (int off = 16; off > 0; off >>= 1)
            p += __shfl_xor_sync(0xffffffffu, p, off);
        accum(1.f / (1.f + __expf(-(p + bb))), hraw);
    }

    if (MODE == 1) {
        float* op = &outf[(size_t)d * CH + lane * 8];
        *reinterpret_cast<float4*>(op)     = make_float4(acc0, acc1, acc2, acc3);
        *reinterpret_cast<float4*>(op + 4) = make_float4(acc4, acc5, acc6, acc7);
    } else {
        float r[8] = {fmaxf(acc0, 0.f), fmaxf(acc1, 0.f), fmaxf(acc2, 0.f), fmaxf(acc3, 0.f),
                      fmaxf(acc4, 0.f), fmaxf(acc5, 0.f), fmaxf(acc6, 0.f), fmaxf(acc7, 0.f)};
        __half h[8], l[8];
        #pragma unroll
        for (int q = 0; q < 8; q++) {
            h[q] = __float2half_rn(r[q]);
            l[q] = __float2half_rn(r[q] - __half2float(h[q]));
        }
        uint4 hv, lv;
        hv.x = *reinterpret_cast<unsigned*>(&__halves2half2(h[0], h[1]));
        hv.y = *reinterpret_cast<unsigned*>(&__halves2half2(h[2], h[3]));
        hv.z = *reinterpret_cast<unsigned*>(&__halves2half2(h[4], h[5]));
        hv.w = *reinterpret_cast<unsigned*>(&__halves2half2(h[6], h[7]));
        lv.x = *reinterpret_cast<unsigned*>(&__halves2half2(l[0], l[1]));
        lv.y = *reinterpret_cast<unsigned*>(&__halves2half2(l[2], l[3]));
        lv.z = *reinterpret_cast<unsigned*>(&__halves2half2(l[4], l[5]));
        lv.w = *reinterpret_cast<unsigned*>(&__halves2half2(l[6], l[7]));
        *reinterpret_cast<uint4*>(&ohi[(size_t)d * CH + lane * 8]) = hv;
        *reinterpret_cast<uint4*>(&olo[(size_t)d * CH + lane * 8]) = lv;
    }
}

extern "C" void kernel_launch(void* const* d_in, const int* in_sizes, int n_in,
                              void* d_out, int out_size)
{
    (void)in_sizes; (void)n_in; (void)out_size;
    const float* x  = (const float*)d_in[0];
    const int*   ei = (const int*)d_in[1];
    const float* W_lin[3] = {(const float*)d_in[2],  (const float*)d_in[8],  (const float*)d_in[14]};
    const float* b_lin[3] = {(const float*)d_in[3],  (const float*)d_in[9],  (const float*)d_in[15]};
    const float* W_s1[3]  = {(const float*)d_in[4],  (const float*)d_in[10], (const float*)d_in[16]};
    const float* b_s1[3]  = {(const float*)d_in[5],  (const float*)d_in[11], (const float*)d_in[17]};
    const float* W_s2[3]  = {(const float*)d_in[6],  (const float*)d_in[12], (const float*)d_in[18]};
    const float* b_s2[3]  = {(const float*)d_in[7],  (const float*)d_in[13], (const float*)d_in[19]};

    __half *xhi, *xlo, *Hhi, *Ahi, *Alo, *AB;
    cudaGetSymbolAddress((void**)&xhi, g_xhi);
    cudaGetSymbolAddress((void**)&xlo, g_xlo);
    cudaGetSymbolAddress((void**)&Hhi, g_Hhi);
    cudaGetSymbolAddress((void**)&Ahi, g_Ahi);
    cudaGetSymbolAddress((void**)&Alo, g_Alo);
    cudaGetSymbolAddress((void**)&AB,  g_AB);
    float* out = (float*)d_out;

    const dim3 blk(256);
    const dim3 gL((NNODES + 127) / 128, 768 / 64);   // (79, 12)
    const dim3 gWc12(4, 4, 2);
    const int  agrid = (NNODES + 7) / 8;

    // Fork/join resources (host-side objects only; replays execute the graph).
    cudaStream_t side;
    cudaEvent_t  evFork1, evFork2, evJoin1, evJoin2;
    cudaStreamCreateWithFlags(&side, cudaStreamNonBlocking);
    cudaEventCreateWithFlags(&evFork1, cudaEventDisableTiming);
    cudaEventCreateWithFlags(&evFork2, cudaEventDisableTiming);
    cudaEventCreateWithFlags(&evJoin1, cudaEventDisableTiming);
    cudaEventCreateWithFlags(&evJoin2, cudaEventDisableTiming);

    // ---- fork at launch: CSR chain on side stream (outputs g_cnt/g_rowptr/
    //      g_col are disjoint from cvt_all outputs), cvt on main ----
    cudaEventRecord(evFork1, 0);
    cudaStreamWaitEvent(side, evFork1, 0);
    hist_kernel<<<(NEDGES + 255) / 256, blk, 0, side>>>(ei);
    scan_kernel<<<1, 1024, 0, side>>>();
    scatter_kernel<<<(NEDGES + 255) / 256, blk, 0, side>>>(ei);
    cudaEventRecord(evJoin1, side);

    cvt_all<<<(E_BI + 255) / 256, blk>>>(x, W_lin[0], W_lin[1], W_lin[2],
                                         W_s1[0], W_s1[1], W_s1[2],
                                         b_lin[0], b_lin[1], b_lin[2],
                                         b_s1[0], b_s1[1], b_s1[2]);

    // side stream: Wc[1..2] after cvt outputs are ready (overlaps agg1)
    cudaEventRecord(evFork2, 0);
    cudaStreamWaitEvent(side, evFork2, 0);
    wc_gemm12<<<gWc12, blk, 0, side>>>();
    cudaEventRecord(evJoin2, side);

    // main stream: Wc[0] (tiny) + layer-1 GEMM
    wc_gemm0<<<4, blk>>>();
    layer_gemm<<<gL, blk>>>(xhi, xlo, 0, 64, Hhi, AB);

    // join 1: agg1 needs g_col/g_rowptr
    cudaStreamWaitEvent(0, evJoin1, 0);
    agg_kernel<0><<<agrid, blk>>>(AB, Hhi, W_s2[0], b_s2[0], nullptr, Ahi, Alo);

    // join 2: layer 2 needs Wc[1] (and later Wc[2])
    cudaStreamWaitEvent(0, evJoin2, 0);
    layer_gemm<<<gL, blk>>>(Ahi, Alo, 1, 256, Hhi, AB);
    agg_kernel<0><<<agrid, blk>>>(AB, Hhi, W_s2[1], b_s2[1], nullptr, Ahi, Alo);

    // ---- layer 3 (writes d_out) ----
    layer_gemm<<<gL, blk>>>(Ahi, Alo, 2, 256, Hhi, AB);
    agg_kernel<1><<<agrid, blk>>>(AB, Hhi, W_s2[2], b_s2[2], out, nullptr, nullptr);
}

// round 16
// speedup vs baseline: 1.1583x; 1.1271x over previous
#include <cuda_runtime.h>
#include <cuda_fp16.h>
#include <cstdint>

#define NNODES 10000
#define NEDGES 320000
#define CH     256

// ---- scratch (static device allocations; no cudaMalloc allowed) ----
__device__ __align__(16) __half g_xhi[NNODES * 64];
__device__ __align__(16) __half g_xlo[NNODES * 64];
__device__ __align__(16) __half g_Hhi[NNODES * CH];
__device__ __align__(16) __half g_Ahi[NNODES * CH];   // relu(agg) split, next-layer input
__device__ __align__(16) __half g_Alo[NNODES * CH];
__device__ __align__(16) __half g_AB [NNODES * 2 * CH];
__device__ __align__(16) __half g_Wlhi[3][CH * CH];       // W_lin fp16 (layer0: 256x64)
__device__ __align__(16) __half g_WlThi[3][CH * CH];      // W_lin^T fp16 (rows k_in, cols m)
__device__ __align__(16) __half g_Wshi[3][2 * CH * CH];   // W_s1 uniform [512,256] split
__device__ __align__(16) __half g_Wslo[3][2 * CH * CH];
__device__ __align__(16) __half g_Wchi[3][2 * CH * CH];   // Wc = Ws @ Wlin  [512, K_l] fp16
__device__ float g_b768[3][768];                          // [b_lin | Ws@b_lin + b_s1pad]
__device__ int g_rowptr[NNODES + 1];
__device__ int g_cnt[NNODES];   // starts 0; hist fills; scatter's atomicSub restores to 0
__device__ int g_col[NEDGES];

__device__ __forceinline__ uint32_t sptr(const void* p) {
    return (uint32_t)__cvta_generic_to_shared(p);
}
__device__ __forceinline__ void cpa16(uint32_t dst, const void* src, bool pred) {
    int sz = pred ? 16 : 0;
    asm volatile("cp.async.cg.shared.global [%0], [%1], 16, %2;"
                 :: "r"(dst), "l"(src), "r"(sz));
}
__device__ __forceinline__ void cpa_commit() {
    asm volatile("cp.async.commit_group;" ::: "memory");
}

__device__ __forceinline__ void split4(float4 v, uint2& hi, uint2& lo) {
    __half h0 = __float2half_rn(v.x), h1 = __float2half_rn(v.y);
    __half h2 = __float2half_rn(v.z), h3 = __float2half_rn(v.w);
    __half l0 = __float2half_rn(v.x - __half2float(h0));
    __half l1 = __float2half_rn(v.y - __half2float(h1));
    __half l2 = __float2half_rn(v.z - __half2float(h2));
    __half l3 = __float2half_rn(v.w - __half2float(h3));
    __half2 ph0 = __halves2half2(h0, h1), ph1 = __halves2half2(h2, h3);
    __half2 pl0 = __halves2half2(l0, l1), pl1 = __halves2half2(l2, l3);
    hi.x = *reinterpret_cast<unsigned*>(&ph0); hi.y = *reinterpret_cast<unsigned*>(&ph1);
    lo.x = *reinterpret_cast<unsigned*>(&pl0); lo.y = *reinterpret_cast<unsigned*>(&pl1);
}

// ============================================================================
// Fused prep kernel (vectorized). Segment chain (warp-aligned boundaries):
//   [0, E_X4)        : x hi/lo split, float4 (160000)
//   [E_X4, E_WL)     : Wlin fp16 copy, float4 (36864)
//   [E_WL, E_WT)     : Wlin^T fp16 scalar gather (147456)
//   [E_WT, E_WS)     : Ws uniform repack + hi/lo split, float4 (98304)
//   [E_WS, E_B1)     : b_lin copy (768)
//   [E_B1, E_B2)     : bias matvec, ONE WARP PER (layer,row) (1536 warps)
// E_WS = 442624 (mult of 32), copy span 768 (mult of 32) -> warp aligned.
// ============================================================================
#define E_X4  (NNODES * 64 / 4)
#define E_WL  (E_X4 + 147456 / 4)
#define E_WT  (E_WL + 147456)
#define E_WS  (E_WT + 393216 / 4)
#define E_B1  (E_WS + 768)
#define E_B2  (E_B1 + 1536 * 32)

__global__ void __launch_bounds__(256) cvt_all(
    const float* __restrict__ x,
    const float* __restrict__ Wl1, const float* __restrict__ Wl2, const float* __restrict__ Wl3,
    const float* __restrict__ Ws1, const float* __restrict__ Ws2, const float* __restrict__ Ws3,
    const float* __restrict__ bl1, const float* __restrict__ bl2, const float* __restrict__ bl3,
    const float* __restrict__ bs1, const float* __restrict__ bs2, const float* __restrict__ bs3)
{
    int i = blockIdx.x * blockDim.x + threadIdx.x;
    if (i >= E_B2) return;
    if (i < E_X4) {                       // x hi/lo split, 4 elems
        float4 v = reinterpret_cast<const float4*>(x)[i];
        uint2 hi, lo;
        split4(v, hi, lo);
        reinterpret_cast<uint2*>(g_xhi)[i] = hi;
        reinterpret_cast<uint2*>(g_xlo)[i] = lo;
        return;
    }
    if (i < E_WL) {                       // Wlin fp16 copy, 4 elems
        int q = i - E_X4;                 // 0..36863 (layer bounds: 4096, 20480)
        int l, u; const float* W;
        if (q < 4096)        { l = 0; u = q;         W = Wl1; }
        else if (q < 20480)  { l = 1; u = q - 4096;  W = Wl2; }
        else                 { l = 2; u = q - 20480; W = Wl3; }
        float4 v = reinterpret_cast<const float4*>(W)[u];
        __half2 p0 = __floats2half2_rn(v.x, v.y);
        __half2 p1 = __floats2half2_rn(v.z, v.w);
        uint2 pk;
        pk.x = *reinterpret_cast<unsigned*>(&p0);
        pk.y = *reinterpret_cast<unsigned*>(&p1);
        reinterpret_cast<uint2*>(g_Wlhi[l])[u] = pk;
        return;
    }
    if (i < E_WT) {                       // Wlin^T fp16 scalar gather
        int q = i - E_WL;                 // 0..147455 (bounds: 16384, 81920)
        int l, j, kin; const float* W;
        if (q < 16384)       { l = 0; j = q;         W = Wl1; kin = 64; }
        else if (q < 81920)  { l = 1; j = q - 16384; W = Wl2; kin = 256; }
        else                 { l = 2; j = q - 81920; W = Wl3; kin = 256; }
        int k = j >> 8, m = j & 255;
        g_WlThi[l][j] = __float2half_rn(W[m * kin + k]);
        return;
    }
    if (i < E_WS) {                       // Ws uniform repack + hi/lo split, 4 elems
        int q = i - E_WT;                 // 0..98303, 32768 per layer
        int l = q >> 15, u = q & 32767;
        const float* W = (l == 0) ? Ws1 : (l == 1) ? Ws2 : Ws3;
        int j = u * 4;                    // element index in uniform [512,256]
        int r = j >> 8, k = j & 255;      // k%4==0, never crosses a row
        const float* src = (r < CH) ? (W + r * 2 * CH + k)
                                    : (W + (r - CH) * 2 * CH + CH + k);
        float4 v = *reinterpret_cast<const float4*>(src);
        uint2 hi, lo;
        split4(v, hi, lo);
        reinterpret_cast<uint2*>(g_Wshi[l])[u] = hi;
        reinterpret_cast<uint2*>(g_Wslo[l])[u] = lo;
        return;
    }
    if (i < E_B1) {                       // b_lin copy (first 256 of each b768)
        int q = i - E_WS;                 // 0..767
        int l = q >> 8, j = q & 255;
        const float* bl = (l == 0) ? bl1 : (l == 1) ? bl2 : bl3;
        g_b768[l][j] = bl[j];
        return;
    }
    {                                     // bias matvec: one warp per (l, r)
        int q    = i - E_B1;              // warp-aligned segment start
        int w    = q >> 5;                // 0..1535
        int lane = q & 31;
        int l    = w >> 9;                // w / 512
        int r    = w & 511;               // row in uniform [512,256]
        const float* Ws = (l == 0) ? Ws1 : (l == 1) ? Ws2 : Ws3;
        const float* bl = (l == 0) ? bl1 : (l == 1) ? bl2 : bl3;
        const float* bs = (l == 0) ? bs1 : (l == 1) ? bs2 : bs3;
        const float* row = (r < CH) ? (Ws + r * 2 * CH) : (Ws + (r - CH) * 2 * CH + CH);
        float acc = 0.f;
        #pragma unroll
        for (int t = 0; t < 8; t++) {
            int m = lane + 32 * t;
            acc = fmaf(row[m], bl[m], acc);
        }
        #pragma unroll
        for (int off = 16; off > 0; off >>= 1)
            acc += __shfl_xor_sync(0xffffffffu, acc, off);
        if (lane == 0)
            g_b768[l][256 + r] = acc + ((r < CH) ? bs[r] : 0.f);
    }
}

__global__ void __launch_bounds__(256) hist_kernel(const int* __restrict__ ei) {
    int e = blockIdx.x * blockDim.x + threadIdx.x;
    if (e < NEDGES) atomicAdd(&g_cnt[ei[NEDGES + e]], 1);
}

// ============================================================================
// Single-pass scan: 1024 threads x 10 elements, 2 barriers total.
// Does NOT modify g_cnt (scatter restores it to zero).
// ============================================================================
__global__ void __launch_bounds__(1024) scan_kernel() {
    __shared__ int wsum[32];
    const int t = threadIdx.x, lane = t & 31, w = t >> 5;
    const int base_i = t * 10;
    int v[10];
    int s = 0;
    #pragma unroll
    for (int q = 0; q < 10; q++) {
        int idx = base_i + q;
        v[q] = (idx < NNODES) ? g_cnt[idx] : 0;
        s += v[q];
    }
    int x = s;
    #pragma unroll
    for (int o = 1; o < 32; o <<= 1) {
        int y = __shfl_up_sync(0xffffffffu, x, o);
        if (lane >= o) x += y;
    }
    if (lane == 31) wsum[w] = x;
    __syncthreads();
    if (w == 0) {
        int z = wsum[lane];
        #pragma unroll
        for (int o = 1; o < 32; o <<= 1) {
            int y = __shfl_up_sync(0xffffffffu, z, o);
            if (lane >= o) z += y;
        }
        wsum[lane] = z;
    }
    __syncthreads();
    int run = (x - s) + (w > 0 ? wsum[w - 1] : 0);
    #pragma unroll
    for (int q = 0; q < 10; q++) {
        int idx = base_i + q;
        if (idx < NNODES) g_rowptr[idx] = run;
        run += v[q];
    }
    if (t == 1023) g_rowptr[NNODES] = wsum[31];
}

// scatter restores g_cnt to all-zero (atomicSub), keeping replays deterministic.
__global__ void scatter_kernel(const int* __restrict__ ei) {
    int e = blockIdx.x * blockDim.x + threadIdx.x;
    if (e < NEDGES) {
        int s = ei[e];
        int d = ei[NEDGES + e];
        int old = atomicSub(&g_cnt[d], 1);
        g_col[g_rowptr[d] + old - 1] = s;
    }
}

// ============================================================================
// GEMM core (R12 config — frozen): 2-region split, BM=128 BN=64 BK=64,
// 8 warps, warp tile 32x32, 2-stage cp.async, 128B-row XOR swizzle.
// ============================================================================
template<int OUTMODE, bool DUALW>
__device__ __forceinline__ void gemm_core(
    const __half* __restrict__ Ahi, const __half* __restrict__ Alo,
    const __half* __restrict__ Wahi, const __half* __restrict__ Wbhi,
    const float* __restrict__ bias,
    __half* __restrict__ out0, __half* __restrict__ out1,
    int M, int K, int ostride, int bm, int bn)
{
    constexpr int BM = 128, BN = 64, BK = 64;
    __shared__ __align__(16) __half sA[2][BM * BK];   // 32 KB
    __shared__ __align__(16) __half sB[2][BN * BK];   // 16 KB

    const int tid  = threadIdx.x;
    const int lane = tid & 31;
    const int warp = tid >> 5;
    const int wm   = (warp >> 1) * 32;
    const int wn   = (warp & 1) * 32;
    const int nch  = (2 * K) / BK;

    const int chunk = tid & 7;
    const int rbase = tid >> 3;

    const bool useB = DUALW && (bn >= 256);
    const int  nb   = useB ? bn - 256 : bn;
    const __half* Whi = useB ? Wbhi : Wahi;

    float c[2][4][4];
    #pragma unroll
    for (int i = 0; i < 2; i++)
        #pragma unroll
        for (int j = 0; j < 4; j++)
            #pragma unroll
            for (int q = 0; q < 4; q++) c[i][j][q] = 0.f;

    auto issue = [&](int ch) {
        int buf = ch & 1;
        int k0v = ch * BK;
        int region = k0v / K;
        int kreal  = k0v - region * K;
        const __half* As = (region == 1) ? Alo : Ahi;
        uint32_t baseA = sptr(&sA[buf][0]);
        uint32_t baseB = sptr(&sB[buf][0]);
        #pragma unroll
        for (int i = 0; i < 4; i++) {
            int row = rbase + 32 * i;
            int gm  = bm + row;
            bool ok = gm < M;
            const __half* src = As + (size_t)(ok ? gm : 0) * K + kreal + chunk * 8;
            cpa16(baseA + row * 128 + ((chunk ^ (row & 7)) << 4), src, ok);
        }
        #pragma unroll
        for (int i = 0; i < 2; i++) {
            int row = rbase + 32 * i;
            const __half* src = Whi + (size_t)(nb + row) * K + kreal + chunk * 8;
            cpa16(baseB + row * 128 + ((chunk ^ (row & 7)) << 4), src, true);
        }
        cpa_commit();
    };

    auto compute = [&](int buf) {
        uint32_t baseA = sptr(&sA[buf][0]);
        uint32_t baseB = sptr(&sB[buf][0]);
        #pragma unroll
        for (int kk = 0; kk < 4; kk++) {
            int cl = kk * 2 + (lane >> 4);
            uint32_t bf[2][4];
            #pragma unroll
            for (int h = 0; h < 2; h++) {
                int row = wn + h * 16 + (lane & 15);
                uint32_t p = baseB + row * 128 + ((cl ^ (row & 7)) << 4);
                asm volatile("ldmatrix.sync.aligned.m8n8.x4.shared.b16 {%0,%1,%2,%3}, [%4];"
                             : "=r"(bf[h][0]), "=r"(bf[h][1]), "=r"(bf[h][2]), "=r"(bf[h][3]) : "r"(p));
            }
            #pragma unroll
            for (int fi = 0; fi < 2; fi++) {
                uint32_t a0, a1, a2, a3;
                int row = wm + fi * 16 + (lane & 15);
                uint32_t p = baseA + row * 128 + ((cl ^ (row & 7)) << 4);
                asm volatile("ldmatrix.sync.aligned.m8n8.x4.shared.b16 {%0,%1,%2,%3}, [%4];"
                             : "=r"(a0), "=r"(a1), "=r"(a2), "=r"(a3) : "r"(p));
                #pragma unroll
                for (int h = 0; h < 2; h++) {
                    asm volatile("mma.sync.aligned.m16n8k16.row.col.f32.f16.f16.f32 "
                                 "{%0,%1,%2,%3}, {%4,%5,%6,%7}, {%8,%9}, {%0,%1,%2,%3};"
                                 : "+f"(c[fi][2*h+0][0]), "+f"(c[fi][2*h+0][1]), "+f"(c[fi][2*h+0][2]), "+f"(c[fi][2*h+0][3])
                                 : "r"(a0), "r"(a1), "r"(a2), "r"(a3), "r"(bf[h][0]), "r"(bf[h][2]));
                    asm volatile("mma.sync.aligned.m16n8k16.row.col.f32.f16.f16.f32 "
                                 "{%0,%1,%2,%3}, {%4,%5,%6,%7}, {%8,%9}, {%0,%1,%2,%3};"
                                 : "+f"(c[fi][2*h+1][0]), "+f"(c[fi][2*h+1][1]), "+f"(c[fi][2*h+1][2]), "+f"(c[fi][2*h+1][3])
                                 : "r"(a0), "r"(a1), "r"(a2), "r"(a3), "r"(bf[h][1]), "r"(bf[h][3]));
                }
            }
        }
    };

    issue(0);
    if (nch > 1) issue(1);
    for (int ch = 0; ch < nch; ch++) {
        if (ch + 1 < nch) asm volatile("cp.async.wait_group 1;" ::: "memory");
        else              asm volatile("cp.async.wait_group 0;" ::: "memory");
        __syncthreads();
        compute(ch & 1);
        __syncthreads();
        if (ch + 2 < nch) issue(ch + 2);
    }

    // ---- epilogue ----
    __half* dst;
    int stride, cb;
    if (OUTMODE == 1) {
        dst    = useB ? out1 : out0;
        stride = useB ? 512 : 256;
        cb     = nb;
    } else {
        dst    = out0;
        stride = ostride;
        cb     = bn;
    }
    #pragma unroll
    for (int fi = 0; fi < 2; fi++) {
        int row0 = bm + wm + fi * 16 + (lane >> 2);
        #pragma unroll
        for (int nj = 0; nj < 4; nj++) {
            int cl = wn + nj * 8 + (lane & 3) * 2;
            float bx = 0.f, by = 0.f;
            if (OUTMODE == 1) { bx = bias[bn + cl]; by = bias[bn + cl + 1]; }
            float v0 = c[fi][nj][0] + bx, v1 = c[fi][nj][1] + by;
            float v2 = c[fi][nj][2] + bx, v3 = c[fi][nj][3] + by;
            int col = cb + cl;
            if (row0 < M)
                *reinterpret_cast<__half2*>(&dst[(size_t)row0 * stride + col]) = __floats2half2_rn(v0, v1);
            if (row0 + 8 < M)
                *reinterpret_cast<__half2*>(&dst[(size_t)(row0 + 8) * stride + col]) = __floats2half2_rn(v2, v3);
        }
    }
}

// Wc precompute, layer 0 only: Wc[0] = Ws[0](split) @ WlT[0] -> fp16 [512, 64]
__global__ void __launch_bounds__(256) wc_gemm0() {
    gemm_core<2, false>(g_Wshi[0], g_Wslo[0], g_WlThi[0], nullptr,
                        nullptr, g_Wchi[0], nullptr, 512, 256, 64,
                        blockIdx.x * 128, 0);
}

// Wc precompute, layers 1-2 (side stream, overlapped with agg1)
__global__ void __launch_bounds__(256) wc_gemm12() {
    int l = blockIdx.z + 1;
    gemm_core<2, false>(g_Wshi[l], g_Wslo[l], g_WlThi[l], nullptr,
                        nullptr, g_Wchi[l], nullptr, 512, 256, 256,
                        blockIdx.x * 128, blockIdx.y * 64);
}

// Fused per-layer GEMM: [Hhi | AB] = relu_in @ [Wlin ; Wc]^T + b768
__global__ void __launch_bounds__(256) layer_gemm(
    const __half* __restrict__ Ahi, const __half* __restrict__ Alo,
    int l, int K, __half* __restrict__ Hhi, __half* __restrict__ AB)
{
    gemm_core<1, true>(Ahi, Alo, g_Wlhi[l], g_Wchi[l],
                       g_b768[l], Hhi, AB, NNODES, K, 0,
                       blockIdx.x * 128, blockIdx.y * 64);
}

// ============================================================================
// Fused score + aggregate: one warp per dst node (CSR), no atomics.
// 2-edge ILP. MODE 0: relu-split hi/lo fp16 out. MODE 1: fp32 out (final).
// ============================================================================
template<int MODE>
__global__ void __launch_bounds__(256) agg_kernel(
    const __half* __restrict__ AB,
    const __half* __restrict__ Hhi,
    const float* __restrict__ w2, const float* __restrict__ b2,
    float* __restrict__ outf, __half* __restrict__ ohi, __half* __restrict__ olo)
{
    const int lane = threadIdx.x & 31;
    const int d    = blockIdx.x * (blockDim.x >> 5) + (threadIdx.x >> 5);
    if (d >= NNODES) return;

    const float4 w0 = *reinterpret_cast<const float4*>(&w2[lane * 8]);
    const float4 w1 = *reinterpret_cast<const float4*>(&w2[lane * 8 + 4]);
    const float  bb = b2[0];

    uint4 araw = *reinterpret_cast<const uint4*>(&AB[(size_t)d * (2 * CH) + lane * 8]);
    float2 a0 = __half22float2(*reinterpret_cast<__half2*>(&araw.x));
    float2 a1 = __half22float2(*reinterpret_cast<__half2*>(&araw.y));
    float2 a2 = __half22float2(*reinterpret_cast<__half2*>(&araw.z));
    float2 a3 = __half22float2(*reinterpret_cast<__half2*>(&araw.w));

    float acc0 = 0.f, acc1 = 0.f, acc2 = 0.f, acc3 = 0.f;
    float acc4 = 0.f, acc5 = 0.f, acc6 = 0.f, acc7 = 0.f;

    auto partial = [&](int s, uint4& hraw) -> float {
        uint4 braw = *reinterpret_cast<const uint4*>(&AB[(size_t)s * (2 * CH) + CH + lane * 8]);
        hraw = *reinterpret_cast<const uint4*>(&Hhi[(size_t)s * CH + lane * 8]);
        float2 b0 = __half22float2(*reinterpret_cast<__half2*>(&braw.x));
        float2 b1 = __half22float2(*reinterpret_cast<__half2*>(&braw.y));
        float2 b2v = __half22float2(*reinterpret_cast<__half2*>(&braw.z));
        float2 b3 = __half22float2(*reinterpret_cast<__half2*>(&braw.w));
        float p;
        p  = fmaxf(a0.x + b0.x, 0.f) * w0.x;
        p += fmaxf(a0.y + b0.y, 0.f) * w0.y;
        p += fmaxf(a1.x + b1.x, 0.f) * w0.z;
        p += fmaxf(a1.y + b1.y, 0.f) * w0.w;
        p += fmaxf(a2.x + b2v.x, 0.f) * w1.x;
        p += fmaxf(a2.y + b2v.y, 0.f) * w1.y;
        p += fmaxf(a3.x + b3.x, 0.f) * w1.z;
        p += fmaxf(a3.y + b3.y, 0.f) * w1.w;
        return p;
    };

    auto accum = [&](float score, const uint4& hraw) {
        float2 h0 = __half22float2(*reinterpret_cast<const __half2*>(&hraw.x));
        float2 h1 = __half22float2(*reinterpret_cast<const __half2*>(&hraw.y));
        float2 h2 = __half22float2(*reinterpret_cast<const __half2*>(&hraw.z));
        float2 h3 = __half22float2(*reinterpret_cast<const __half2*>(&hraw.w));
        acc0 = fmaf(score, h0.x, acc0);
        acc1 = fmaf(score, h0.y, acc1);
        acc2 = fmaf(score, h1.x, acc2);
        acc3 = fmaf(score, h1.y, acc3);
        acc4 = fmaf(score, h2.x, acc4);
        acc5 = fmaf(score, h2.y, acc5);
        acc6 = fmaf(score, h3.x, acc6);
        acc7 = fmaf(score, h3.y, acc7);
    };

    const int beg = g_rowptr[d];
    const int end = g_rowptr[d + 1];

    // self-loop first
    {
        uint4 hraw;
        float p = partial(d, hraw);
        #pragma unroll
        for (int off = 16; off > 0; off >>= 1)
            p += __shfl_xor_sync(0xffffffffu, p, off);
        accum(1.f / (1.f + __expf(-(p + bb))), hraw);
    }

    int i = beg;
    for (; i + 1 < end; i += 2) {
        int s0 = g_col[i];
        int s1 = g_col[i + 1];
        uint4 hraw0, hraw1;
        float p0 = partial(s0, hraw0);
        float p1 = partial(s1, hraw1);
        #pragma unroll
        for (int off = 16; off > 0; off >>= 1) {
            p0 += __shfl_xor_sync(0xffffffffu, p0, off);
            p1 += __shfl_xor_sync(0xffffffffu, p1, off);
        }
        float sc0 = 1.f / (1.f + __expf(-(p0 + bb)));
        float sc1 = 1.f / (1.f + __expf(-(p1 + bb)));
        accum(sc0, hraw0);
        accum(sc1, hraw1);
    }
    if (i < end) {
        uint4 hraw;
        float p = partial(g_col[i], hraw);
        #pragma unroll
        for (int off = 16; off > 0; off >>= 1)
            p += __shfl_xor_sync(0xffffffffu, p, off);
        accum(1.f / (1.f + __expf(-(p + bb))), hraw);
    }

    if (MODE == 1) {
        float* op = &outf[(size_t)d * CH + lane * 8];
        *reinterpret_cast<float4*>(op)     = make_float4(acc0, acc1, acc2, acc3);
        *reinterpret_cast<float4*>(op + 4) = make_float4(acc4, acc5, acc6, acc7);
    } else {
        float r[8] = {fmaxf(acc0, 0.f), fmaxf(acc1, 0.f), fmaxf(acc2, 0.f), fmaxf(acc3, 0.f),
                      fmaxf(acc4, 0.f), fmaxf(acc5, 0.f), fmaxf(acc6, 0.f), fmaxf(acc7, 0.f)};
        __half h[8], l[8];
        #pragma unroll
        for (int q = 0; q < 8; q++) {
            h[q] = __float2half_rn(r[q]);
            l[q] = __float2half_rn(r[q] - __half2float(h[q]));
        }
        uint4 hv, lv;
        hv.x = *reinterpret_cast<unsigned*>(&__halves2half2(h[0], h[1]));
        hv.y = *reinterpret_cast<unsigned*>(&__halves2half2(h[2], h[3]));
        hv.z = *reinterpret_cast<unsigned*>(&__halves2half2(h[4], h[5]));
        hv.w = *reinterpret_cast<unsigned*>(&__halves2half2(h[6], h[7]));
        lv.x = *reinterpret_cast<unsigned*>(&__halves2half2(l[0], l[1]));
        lv.y = *reinterpret_cast<unsigned*>(&__halves2half2(l[2], l[3]));
        lv.z = *reinterpret_cast<unsigned*>(&__halves2half2(l[4], l[5]));
        lv.w = *reinterpret_cast<unsigned*>(&__halves2half2(l[6], l[7]));
        *reinterpret_cast<uint4*>(&ohi[(size_t)d * CH + lane * 8]) = hv;
        *reinterpret_cast<uint4*>(&olo[(size_t)d * CH + lane * 8]) = lv;
    }
}

extern "C" void kernel_launch(void* const* d_in, const int* in_sizes, int n_in,
                              void* d_out, int out_size)
{
    (void)in_sizes; (void)n_in; (void)out_size;
    const float* x  = (const float*)d_in[0];
    const int*   ei = (const int*)d_in[1];
    const float* W_lin[3] = {(const float*)d_in[2],  (const float*)d_in[8],  (const float*)d_in[14]};
    const float* b_lin[3] = {(const float*)d_in[3],  (const float*)d_in[9],  (const float*)d_in[15]};
    const float* W_s1[3]  = {(const float*)d_in[4],  (const float*)d_in[10], (const float*)d_in[16]};
    const float* b_s1[3]  = {(const float*)d_in[5],  (const float*)d_in[11], (const float*)d_in[17]};
    const float* W_s2[3]  = {(const float*)d_in[6],  (const float*)d_in[12], (const float*)d_in[18]};
    const float* b_s2[3]  = {(const float*)d_in[7],  (const float*)d_in[13], (const float*)d_in[19]};

    __half *xhi, *xlo, *Hhi, *Ahi, *Alo, *AB;
    cudaGetSymbolAddress((void**)&xhi, g_xhi);
    cudaGetSymbolAddress((void**)&xlo, g_xlo);
    cudaGetSymbolAddress((void**)&Hhi, g_Hhi);
    cudaGetSymbolAddress((void**)&Ahi, g_Ahi);
    cudaGetSymbolAddress((void**)&Alo, g_Alo);
    cudaGetSymbolAddress((void**)&AB,  g_AB);
    float* out = (float*)d_out;

    const dim3 blk(256);
    const dim3 gL((NNODES + 127) / 128, 768 / 64);   // (79, 12)
    const dim3 gWc12(4, 4, 2);
    const int  agrid = (NNODES + 7) / 8;

    // Fork/join resources (host-side objects only; replays execute the graph).
    cudaStream_t side;
    cudaEvent_t  evFork1, evFork2, evJoin1, evJoin2;
    cudaStreamCreateWithFlags(&side, cudaStreamNonBlocking);
    cudaEventCreateWithFlags(&evFork1, cudaEventDisableTiming);
    cudaEventCreateWithFlags(&evFork2, cudaEventDisableTiming);
    cudaEventCreateWithFlags(&evJoin1, cudaEventDisableTiming);
    cudaEventCreateWithFlags(&evJoin2, cudaEventDisableTiming);

    // ---- fork at launch: CSR chain on side stream (outputs g_cnt/g_rowptr/
    //      g_col are disjoint from cvt_all outputs), cvt on main ----
    cudaEventRecord(evFork1, 0);
    cudaStreamWaitEvent(side, evFork1, 0);
    hist_kernel<<<(NEDGES + 255) / 256, blk, 0, side>>>(ei);
    scan_kernel<<<1, 1024, 0, side>>>();
    scatter_kernel<<<(NEDGES + 255) / 256, blk, 0, side>>>(ei);
    cudaEventRecord(evJoin1, side);

    cvt_all<<<(E_B2 + 255) / 256, blk>>>(x, W_lin[0], W_lin[1], W_lin[2],
                                         W_s1[0], W_s1[1], W_s1[2],
                                         b_lin[0], b_lin[1], b_lin[2],
                                         b_s1[0], b_s1[1], b_s1[2]);

    // side stream: Wc[1..2] after cvt outputs are ready (overlaps agg1)
    cudaEventRecord(evFork2, 0);
    cudaStreamWaitEvent(side, evFork2, 0);
    wc_gemm12<<<gWc12, blk, 0, side>>>();
    cudaEventRecord(evJoin2, side);

    // main stream: Wc[0] (tiny) + layer-1 GEMM
    wc_gemm0<<<4, blk>>>();
    layer_gemm<<<gL, blk>>>(xhi, xlo, 0, 64, Hhi, AB);

    // join 1: agg1 needs g_col/g_rowptr
    cudaStreamWaitEvent(0, evJoin1, 0);
    agg_kernel<0><<<agrid, blk>>>(AB, Hhi, W_s2[0], b_s2[0], nullptr, Ahi, Alo);

    // join 2: layer 2 needs Wc[1] (and later Wc[2])
    cudaStreamWaitEvent(0, evJoin2, 0);
    layer_gemm<<<gL, blk>>>(Ahi, Alo, 1, 256, Hhi, AB);
    agg_kernel<0><<<agrid, blk>>>(AB, Hhi, W_s2[1], b_s2[1], nullptr, Ahi, Alo);

    // ---- layer 3 (writes d_out) ----
    layer_gemm<<<gL, blk>>>(Ahi, Alo, 2, 256, Hhi, AB);
    agg_kernel<1><<<agrid, blk>>>(AB, Hhi, W_s2[2], b_s2[2], out, nullptr, nullptr);
}

// round 17
// speedup vs baseline: 1.2445x; 1.0744x over previous
#include <cuda_runtime.h>
#include <cuda_fp16.h>
#include <cstdint>

#define NNODES 10000
#define NEDGES 320000
#define CH     256
#define HN     5120   // half-split boundary (rows/nodes), multiple of 128 and 8*32

// ---- scratch (static device allocations; no cudaMalloc allowed) ----
__device__ __align__(16) __half g_xhi[NNODES * 64];
__device__ __align__(16) __half g_xlo[NNODES * 64];
__device__ __align__(16) __half g_H  [2][NNODES * CH];      // ping-pong H
__device__ __align__(16) __half g_ABp[2][NNODES * 2 * CH];  // ping-pong AB
__device__ __align__(16) __half g_Ahi[NNODES * CH];   // relu(agg) split, next-layer input
__device__ __align__(16) __half g_Alo[NNODES * CH];
__device__ __align__(16) __half g_Wlhi[3][CH * CH];
__device__ __align__(16) __half g_WlThi[3][CH * CH];
__device__ __align__(16) __half g_Wshi[3][2 * CH * CH];
__device__ __align__(16) __half g_Wslo[3][2 * CH * CH];
__device__ __align__(16) __half g_Wchi[3][2 * CH * CH];
__device__ float g_b768[3][768];
__device__ int g_rowptr[NNODES + 1];
__device__ int g_cnt[NNODES];   // starts 0; hist fills; scatter's atomicSub restores to 0
__device__ int g_col[NEDGES];

__device__ __forceinline__ uint32_t sptr(const void* p) {
    return (uint32_t)__cvta_generic_to_shared(p);
}
__device__ __forceinline__ void cpa16(uint32_t dst, const void* src, bool pred) {
    int sz = pred ? 16 : 0;
    asm volatile("cp.async.cg.shared.global [%0], [%1], 16, %2;"
                 :: "r"(dst), "l"(src), "r"(sz));
}
__device__ __forceinline__ void cpa_commit() {
    asm volatile("cp.async.commit_group;" ::: "memory");
}

__device__ __forceinline__ void split4(float4 v, uint2& hi, uint2& lo) {
    __half h0 = __float2half_rn(v.x), h1 = __float2half_rn(v.y);
    __half h2 = __float2half_rn(v.z), h3 = __float2half_rn(v.w);
    __half l0 = __float2half_rn(v.x - __half2float(h0));
    __half l1 = __float2half_rn(v.y - __half2float(h1));
    __half l2 = __float2half_rn(v.z - __half2float(h2));
    __half l3 = __float2half_rn(v.w - __half2float(h3));
    __half2 ph0 = __halves2half2(h0, h1), ph1 = __halves2half2(h2, h3);
    __half2 pl0 = __halves2half2(l0, l1), pl1 = __halves2half2(l2, l3);
    hi.x = *reinterpret_cast<unsigned*>(&ph0); hi.y = *reinterpret_cast<unsigned*>(&ph1);
    lo.x = *reinterpret_cast<unsigned*>(&pl0); lo.y = *reinterpret_cast<unsigned*>(&pl1);
}

// ============================================================================
// Fused prep kernel (R16 winner, unchanged).
// ============================================================================
#define E_X4  (NNODES * 64 / 4)
#define E_WL  (E_X4 + 147456 / 4)
#define E_WT  (E_WL + 147456)
#define E_WS  (E_WT + 393216 / 4)
#define E_B1  (E_WS + 768)
#define E_B2  (E_B1 + 1536 * 32)

__global__ void __launch_bounds__(256) cvt_all(
    const float* __restrict__ x,
    const float* __restrict__ Wl1, const float* __restrict__ Wl2, const float* __restrict__ Wl3,
    const float* __restrict__ Ws1, const float* __restrict__ Ws2, const float* __restrict__ Ws3,
    const float* __restrict__ bl1, const float* __restrict__ bl2, const float* __restrict__ bl3,
    const float* __restrict__ bs1, const float* __restrict__ bs2, const float* __restrict__ bs3)
{
    int i = blockIdx.x * blockDim.x + threadIdx.x;
    if (i >= E_B2) return;
    if (i < E_X4) {
        float4 v = reinterpret_cast<const float4*>(x)[i];
        uint2 hi, lo;
        split4(v, hi, lo);
        reinterpret_cast<uint2*>(g_xhi)[i] = hi;
        reinterpret_cast<uint2*>(g_xlo)[i] = lo;
        return;
    }
    if (i < E_WL) {
        int q = i - E_X4;
        int l, u; const float* W;
        if (q < 4096)        { l = 0; u = q;         W = Wl1; }
        else if (q < 20480)  { l = 1; u = q - 4096;  W = Wl2; }
        else                 { l = 2; u = q - 20480; W = Wl3; }
        float4 v = reinterpret_cast<const float4*>(W)[u];
        __half2 p0 = __floats2half2_rn(v.x, v.y);
        __half2 p1 = __floats2half2_rn(v.z, v.w);
        uint2 pk;
        pk.x = *reinterpret_cast<unsigned*>(&p0);
        pk.y = *reinterpret_cast<unsigned*>(&p1);
        reinterpret_cast<uint2*>(g_Wlhi[l])[u] = pk;
        return;
    }
    if (i < E_WT) {
        int q = i - E_WL;
        int l, j, kin; const float* W;
        if (q < 16384)       { l = 0; j = q;         W = Wl1; kin = 64; }
        else if (q < 81920)  { l = 1; j = q - 16384; W = Wl2; kin = 256; }
        else                 { l = 2; j = q - 81920; W = Wl3; kin = 256; }
        int k = j >> 8, m = j & 255;
        g_WlThi[l][j] = __float2half_rn(W[m * kin + k]);
        return;
    }
    if (i < E_WS) {
        int q = i - E_WT;
        int l = q >> 15, u = q & 32767;
        const float* W = (l == 0) ? Ws1 : (l == 1) ? Ws2 : Ws3;
        int j = u * 4;
        int r = j >> 8, k = j & 255;
        const float* src = (r < CH) ? (W + r * 2 * CH + k)
                                    : (W + (r - CH) * 2 * CH + CH + k);
        float4 v = *reinterpret_cast<const float4*>(src);
        uint2 hi, lo;
        split4(v, hi, lo);
        reinterpret_cast<uint2*>(g_Wshi[l])[u] = hi;
        reinterpret_cast<uint2*>(g_Wslo[l])[u] = lo;
        return;
    }
    if (i < E_B1) {
        int q = i - E_WS;
        int l = q >> 8, j = q & 255;
        const float* bl = (l == 0) ? bl1 : (l == 1) ? bl2 : bl3;
        g_b768[l][j] = bl[j];
        return;
    }
    {
        int q    = i - E_B1;
        int w    = q >> 5;
        int lane = q & 31;
        int l    = w >> 9;
        int r    = w & 511;
        const float* Ws = (l == 0) ? Ws1 : (l == 1) ? Ws2 : Ws3;
        const float* bl = (l == 0) ? bl1 : (l == 1) ? bl2 : bl3;
        const float* bs = (l == 0) ? bs1 : (l == 1) ? bs2 : bs3;
        const float* row = (r < CH) ? (Ws + r * 2 * CH) : (Ws + (r - CH) * 2 * CH + CH);
        float acc = 0.f;
        #pragma unroll
        for (int t = 0; t < 8; t++) {
            int m = lane + 32 * t;
            acc = fmaf(row[m], bl[m], acc);
        }
        #pragma unroll
        for (int off = 16; off > 0; off >>= 1)
            acc += __shfl_xor_sync(0xffffffffu, acc, off);
        if (lane == 0)
            g_b768[l][256 + r] = acc + ((r < CH) ? bs[r] : 0.f);
    }
}

__global__ void __launch_bounds__(256) hist_kernel(const int* __restrict__ ei) {
    int e = blockIdx.x * blockDim.x + threadIdx.x;
    if (e < NEDGES) atomicAdd(&g_cnt[ei[NEDGES + e]], 1);
}

__global__ void __launch_bounds__(1024) scan_kernel() {
    __shared__ int wsum[32];
    const int t = threadIdx.x, lane = t & 31, w = t >> 5;
    const int base_i = t * 10;
    int v[10];
    int s = 0;
    #pragma unroll
    for (int q = 0; q < 10; q++) {
        int idx = base_i + q;
        v[q] = (idx < NNODES) ? g_cnt[idx] : 0;
        s += v[q];
    }
    int x = s;
    #pragma unroll
    for (int o = 1; o < 32; o <<= 1) {
        int y = __shfl_up_sync(0xffffffffu, x, o);
        if (lane >= o) x += y;
    }
    if (lane == 31) wsum[w] = x;
    __syncthreads();
    if (w == 0) {
        int z = wsum[lane];
        #pragma unroll
        for (int o = 1; o < 32; o <<= 1) {
            int y = __shfl_up_sync(0xffffffffu, z, o);
            if (lane >= o) z += y;
        }
        wsum[lane] = z;
    }
    __syncthreads();
    int run = (x - s) + (w > 0 ? wsum[w - 1] : 0);
    #pragma unroll
    for (int q = 0; q < 10; q++) {
        int idx = base_i + q;
        if (idx < NNODES) g_rowptr[idx] = run;
        run += v[q];
    }
    if (t == 1023) g_rowptr[NNODES] = wsum[31];
}

__global__ void scatter_kernel(const int* __restrict__ ei) {
    int e = blockIdx.x * blockDim.x + threadIdx.x;
    if (e < NEDGES) {
        int s = ei[e];
        int d = ei[NEDGES + e];
        int old = atomicSub(&g_cnt[d], 1);
        g_col[g_rowptr[d] + old - 1] = s;
    }
}

// ============================================================================
// GEMM core (R12 config — frozen), plus bmBase for half-splitting.
// ============================================================================
template<int OUTMODE, bool DUALW>
__device__ __forceinline__ void gemm_core(
    const __half* __restrict__ Ahi, const __half* __restrict__ Alo,
    const __half* __restrict__ Wahi, const __half* __restrict__ Wbhi,
    const float* __restrict__ bias,
    __half* __restrict__ out0, __half* __restrict__ out1,
    int M, int K, int ostride, int bm, int bn)
{
    constexpr int BM = 128, BN = 64, BK = 64;
    __shared__ __align__(16) __half sA[2][BM * BK];
    __shared__ __align__(16) __half sB[2][BN * BK];

    const int tid  = threadIdx.x;
    const int lane = tid & 31;
    const int warp = tid >> 5;
    const int wm   = (warp >> 1) * 32;
    const int wn   = (warp & 1) * 32;
    const int nch  = (2 * K) / BK;

    const int chunk = tid & 7;
    const int rbase = tid >> 3;

    const bool useB = DUALW && (bn >= 256);
    const int  nb   = useB ? bn - 256 : bn;
    const __half* Whi = useB ? Wbhi : Wahi;

    float c[2][4][4];
    #pragma unroll
    for (int i = 0; i < 2; i++)
        #pragma unroll
        for (int j = 0; j < 4; j++)
            #pragma unroll
            for (int q = 0; q < 4; q++) c[i][j][q] = 0.f;

    auto issue = [&](int ch) {
        int buf = ch & 1;
        int k0v = ch * BK;
        int region = k0v / K;
        int kreal  = k0v - region * K;
        const __half* As = (region == 1) ? Alo : Ahi;
        uint32_t baseA = sptr(&sA[buf][0]);
        uint32_t baseB = sptr(&sB[buf][0]);
        #pragma unroll
        for (int i = 0; i < 4; i++) {
            int row = rbase + 32 * i;
            int gm  = bm + row;
            bool ok = gm < M;
            const __half* src = As + (size_t)(ok ? gm : 0) * K + kreal + chunk * 8;
            cpa16(baseA + row * 128 + ((chunk ^ (row & 7)) << 4), src, ok);
        }
        #pragma unroll
        for (int i = 0; i < 2; i++) {
            int row = rbase + 32 * i;
            const __half* src = Whi + (size_t)(nb + row) * K + kreal + chunk * 8;
            cpa16(baseB + row * 128 + ((chunk ^ (row & 7)) << 4), src, true);
        }
        cpa_commit();
    };

    auto compute = [&](int buf) {
        uint32_t baseA = sptr(&sA[buf][0]);
        uint32_t baseB = sptr(&sB[buf][0]);
        #pragma unroll
        for (int kk = 0; kk < 4; kk++) {
            int cl = kk * 2 + (lane >> 4);
            uint32_t bf[2][4];
            #pragma unroll
            for (int h = 0; h < 2; h++) {
                int row = wn + h * 16 + (lane & 15);
                uint32_t p = baseB + row * 128 + ((cl ^ (row & 7)) << 4);
                asm volatile("ldmatrix.sync.aligned.m8n8.x4.shared.b16 {%0,%1,%2,%3}, [%4];"
                             : "=r"(bf[h][0]), "=r"(bf[h][1]), "=r"(bf[h][2]), "=r"(bf[h][3]) : "r"(p));
            }
            #pragma unroll
            for (int fi = 0; fi < 2; fi++) {
                uint32_t a0, a1, a2, a3;
                int row = wm + fi * 16 + (lane & 15);
                uint32_t p = baseA + row * 128 + ((cl ^ (row & 7)) << 4);
                asm volatile("ldmatrix.sync.aligned.m8n8.x4.shared.b16 {%0,%1,%2,%3}, [%4];"
                             : "=r"(a0), "=r"(a1), "=r"(a2), "=r"(a3) : "r"(p));
                #pragma unroll
                for (int h = 0; h < 2; h++) {
                    asm volatile("mma.sync.aligned.m16n8k16.row.col.f32.f16.f16.f32 "
                                 "{%0,%1,%2,%3}, {%4,%5,%6,%7}, {%8,%9}, {%0,%1,%2,%3};"
                                 : "+f"(c[fi][2*h+0][0]), "+f"(c[fi][2*h+0][1]), "+f"(c[fi][2*h+0][2]), "+f"(c[fi][2*h+0][3])
                                 : "r"(a0), "r"(a1), "r"(a2), "r"(a3), "r"(bf[h][0]), "r"(bf[h][2]));
                    asm volatile("mma.sync.aligned.m16n8k16.row.col.f32.f16.f16.f32 "
                                 "{%0,%1,%2,%3}, {%4,%5,%6,%7}, {%8,%9}, {%0,%1,%2,%3};"
                                 : "+f"(c[fi][2*h+1][0]), "+f"(c[fi][2*h+1][1]), "+f"(c[fi][2*h+1][2]), "+f"(c[fi][2*h+1][3])
                                 : "r"(a0), "r"(a1), "r"(a2), "r"(a3), "r"(bf[h][1]), "r"(bf[h][3]));
                }
            }
        }
    };

    issue(0);
    if (nch > 1) issue(1);
    for (int ch = 0; ch < nch; ch++) {
        if (ch + 1 < nch) asm volatile("cp.async.wait_group 1;" ::: "memory");
        else              asm volatile("cp.async.wait_group 0;" ::: "memory");
        __syncthreads();
        compute(ch & 1);
        __syncthreads();
        if (ch + 2 < nch) issue(ch + 2);
    }

    __half* dst;
    int stride, cb;
    if (OUTMODE == 1) {
        dst    = useB ? out1 : out0;
        stride = useB ? 512 : 256;
        cb     = nb;
    } else {
        dst    = out0;
        stride = ostride;
        cb     = bn;
    }
    #pragma unroll
    for (int fi = 0; fi < 2; fi++) {
        int row0 = bm + wm + fi * 16 + (lane >> 2);
        #pragma unroll
        for (int nj = 0; nj < 4; nj++) {
            int cl = wn + nj * 8 + (lane & 3) * 2;
            float bx = 0.f, by = 0.f;
            if (OUTMODE == 1) { bx = bias[bn + cl]; by = bias[bn + cl + 1]; }
            float v0 = c[fi][nj][0] + bx, v1 = c[fi][nj][1] + by;
            float v2 = c[fi][nj][2] + bx, v3 = c[fi][nj][3] + by;
            int col = cb + cl;
            if (row0 < M)
                *reinterpret_cast<__half2*>(&dst[(size_t)row0 * stride + col]) = __floats2half2_rn(v0, v1);
            if (row0 + 8 < M)
                *reinterpret_cast<__half2*>(&dst[(size_t)(row0 + 8) * stride + col]) = __floats2half2_rn(v2, v3);
        }
    }
}

__global__ void __launch_bounds__(256) wc_gemm0() {
    gemm_core<2, false>(g_Wshi[0], g_Wslo[0], g_WlThi[0], nullptr,
                        nullptr, g_Wchi[0], nullptr, 512, 256, 64,
                        blockIdx.x * 128, 0);
}

__global__ void __launch_bounds__(256) wc_gemm12() {
    int l = blockIdx.z + 1;
    gemm_core<2, false>(g_Wshi[l], g_Wslo[l], g_WlThi[l], nullptr,
                        nullptr, g_Wchi[l], nullptr, 512, 256, 256,
                        blockIdx.x * 128, blockIdx.y * 64);
}

// Fused per-layer GEMM: [H | AB] = relu_in @ [Wlin ; Wc]^T + b768
// bmBase selects the node-half (0 or HN).
__global__ void __launch_bounds__(256) layer_gemm(
    const __half* __restrict__ Ahi, const __half* __restrict__ Alo,
    int l, int K, __half* __restrict__ Hout, __half* __restrict__ ABout, int bmBase)
{
    gemm_core<1, true>(Ahi, Alo, g_Wlhi[l], g_Wchi[l],
                       g_b768[l], Hout, ABout, NNODES, K, 0,
                       bmBase + blockIdx.x * 128, blockIdx.y * 64);
}

// ============================================================================
// Fused score + aggregate (body identical to R16): dBase selects node-half.
// ============================================================================
template<int MODE>
__global__ void __launch_bounds__(256) agg_kernel(
    const __half* __restrict__ AB,
    const __half* __restrict__ Hhi,
    const float* __restrict__ w2, const float* __restrict__ b2,
    float* __restrict__ outf, __half* __restrict__ ohi, __half* __restrict__ olo,
    int dBase)
{
    const int lane = threadIdx.x & 31;
    const int d    = dBase + blockIdx.x * (blockDim.x >> 5) + (threadIdx.x >> 5);
    if (d >= NNODES) return;

    const float4 w0 = *reinterpret_cast<const float4*>(&w2[lane * 8]);
    const float4 w1 = *reinterpret_cast<const float4*>(&w2[lane * 8 + 4]);
    const float  bb = b2[0];

    uint4 araw = *reinterpret_cast<const uint4*>(&AB[(size_t)d * (2 * CH) + lane * 8]);
    float2 a0 = __half22float2(*reinterpret_cast<__half2*>(&araw.x));
    float2 a1 = __half22float2(*reinterpret_cast<__half2*>(&araw.y));
    float2 a2 = __half22float2(*reinterpret_cast<__half2*>(&araw.z));
    float2 a3 = __half22float2(*reinterpret_cast<__half2*>(&araw.w));

    float acc0 = 0.f, acc1 = 0.f, acc2 = 0.f, acc3 = 0.f;
    float acc4 = 0.f, acc5 = 0.f, acc6 = 0.f, acc7 = 0.f;

    auto partial = [&](int s, uint4& hraw) -> float {
        uint4 braw = *reinterpret_cast<const uint4*>(&AB[(size_t)s * (2 * CH) + CH + lane * 8]);
        hraw = *reinterpret_cast<const uint4*>(&Hhi[(size_t)s * CH + lane * 8]);
        float2 b0 = __half22float2(*reinterpret_cast<__half2*>(&braw.x));
        float2 b1 = __half22float2(*reinterpret_cast<__half2*>(&braw.y));
        float2 b2v = __half22float2(*reinterpret_cast<__half2*>(&braw.z));
        float2 b3 = __half22float2(*reinterpret_cast<__half2*>(&braw.w));
        float p;
        p  = fmaxf(a0.x + b0.x, 0.f) * w0.x;
        p += fmaxf(a0.y + b0.y, 0.f) * w0.y;
        p += fmaxf(a1.x + b1.x, 0.f) * w0.z;
        p += fmaxf(a1.y + b1.y, 0.f) * w0.w;
        p += fmaxf(a2.x + b2v.x, 0.f) * w1.x;
        p += fmaxf(a2.y + b2v.y, 0.f) * w1.y;
        p += fmaxf(a3.x + b3.x, 0.f) * w1.z;
        p += fmaxf(a3.y + b3.y, 0.f) * w1.w;
        return p;
    };

    auto accum = [&](float score, const uint4& hraw) {
        float2 h0 = __half22float2(*reinterpret_cast<const __half2*>(&hraw.x));
        float2 h1 = __half22float2(*reinterpret_cast<const __half2*>(&hraw.y));
        float2 h2 = __half22float2(*reinterpret_cast<const __half2*>(&hraw.z));
        float2 h3 = __half22float2(*reinterpret_cast<const __half2*>(&hraw.w));
        acc0 = fmaf(score, h0.x, acc0);
        acc1 = fmaf(score, h0.y, acc1);
        acc2 = fmaf(score, h1.x, acc2);
        acc3 = fmaf(score, h1.y, acc3);
        acc4 = fmaf(score, h2.x, acc4);
        acc5 = fmaf(score, h2.y, acc5);
        acc6 = fmaf(score, h3.x, acc6);
        acc7 = fmaf(score, h3.y, acc7);
    };

    const int beg = g_rowptr[d];
    const int end = g_rowptr[d + 1];

    {
        uint4 hraw;
        float p = partial(d, hraw);
        #pragma unroll
        for (int off = 16; off > 0; off >>= 1)
            p += __shfl_xor_sync(0xffffffffu, p, off);
        accum(1.f / (1.f + __expf(-(p + bb))), hraw);
    }

    int i = beg;
    for (; i + 1 < end; i += 2) {
        int s0 = g_col[i];
        int s1 = g_col[i + 1];
        uint4 hraw0, hraw1;
        float p0 = partial(s0, hraw0);
        float p1 = partial(s1, hraw1);
        #pragma unroll
        for (int off = 16; off > 0; off >>= 1) {
            p0 += __shfl_xor_sync(0xffffffffu, p0, off);
            p1 += __shfl_xor_sync(0xffffffffu, p1, off);
        }
        float sc0 = 1.f / (1.f + __expf(-(p0 + bb)));
        float sc1 = 1.f / (1.f + __expf(-(p1 + bb)));
        accum(sc0, hraw0);
        accum(sc1, hraw1);
    }
    if (i < end) {
        uint4 hraw;
        float p = partial(g_col[i], hraw);
        #pragma unroll
        for (int off = 16; off > 0; off >>= 1)
            p += __shfl_xor_sync(0xffffffffu, p, off);
        accum(1.f / (1.f + __expf(-(p + bb))), hraw);
    }

    if (MODE == 1) {
        float* op = &outf[(size_t)d * CH + lane * 8];
        *reinterpret_cast<float4*>(op)     = make_float4(acc0, acc1, acc2, acc3);
        *reinterpret_cast<float4*>(op + 4) = make_float4(acc4, acc5, acc6, acc7);
    } else {
        float r[8] = {fmaxf(acc0, 0.f), fmaxf(acc1, 0.f), fmaxf(acc2, 0.f), fmaxf(acc3, 0.f),
                      fmaxf(acc4, 0.f), fmaxf(acc5, 0.f), fmaxf(acc6, 0.f), fmaxf(acc7, 0.f)};
        __half h[8], l[8];
        #pragma unroll
        for (int q = 0; q < 8; q++) {
            h[q] = __float2half_rn(r[q]);
            l[q] = __float2half_rn(r[q] - __half2float(h[q]));
        }
        uint4 hv, lv;
        hv.x = *reinterpret_cast<unsigned*>(&__halves2half2(h[0], h[1]));
        hv.y = *reinterpret_cast<unsigned*>(&__halves2half2(h[2], h[3]));
        hv.z = *reinterpret_cast<unsigned*>(&__halves2half2(h[4], h[5]));
        hv.w = *reinterpret_cast<unsigned*>(&__halves2half2(h[6], h[7]));
        lv.x = *reinterpret_cast<unsigned*>(&__halves2half2(l[0], l[1]));
        lv.y = *reinterpret_cast<unsigned*>(&__halves2half2(l[2], l[3]));
        lv.z = *reinterpret_cast<unsigned*>(&__halves2half2(l[4], l[5]));
        lv.w = *reinterpret_cast<unsigned*>(&__halves2half2(l[6], l[7]));
        *reinterpret_cast<uint4*>(&ohi[(size_t)d * CH + lane * 8]) = hv;
        *reinterpret_cast<uint4*>(&olo[(size_t)d * CH + lane * 8]) = lv;
    }
}

extern "C" void kernel_launch(void* const* d_in, const int* in_sizes, int n_in,
                              void* d_out, int out_size)
{
    (void)in_sizes; (void)n_in; (void)out_size;
    const float* x  = (const float*)d_in[0];
    const int*   ei = (const int*)d_in[1];
    const float* W_lin[3] = {(const float*)d_in[2],  (const float*)d_in[8],  (const float*)d_in[14]};
    const float* b_lin[3] = {(const float*)d_in[3],  (const float*)d_in[9],  (const float*)d_in[15]};
    const float* W_s1[3]  = {(const float*)d_in[4],  (const float*)d_in[10], (const float*)d_in[16]};
    const float* b_s1[3]  = {(const float*)d_in[5],  (const float*)d_in[11], (const float*)d_in[17]};
    const float* W_s2[3]  = {(const float*)d_in[6],  (const float*)d_in[12], (const float*)d_in[18]};
    const float* b_s2[3]  = {(const float*)d_in[7],  (const float*)d_in[13], (const float*)d_in[19]};

    __half *xhi, *xlo, *Ahi, *Alo, *H01, *AB01;
    cudaGetSymbolAddress((void**)&xhi,  g_xhi);
    cudaGetSymbolAddress((void**)&xlo,  g_xlo);
    cudaGetSymbolAddress((void**)&Ahi,  g_Ahi);
    cudaGetSymbolAddress((void**)&Alo,  g_Alo);
    cudaGetSymbolAddress((void**)&H01,  g_H);
    cudaGetSymbolAddress((void**)&AB01, g_ABp);
    __half* Hb[2]  = {H01,  H01  + NNODES * CH};
    __half* ABb[2] = {AB01, AB01 + NNODES * 2 * CH};
    float* out = (float*)d_out;

    const dim3 blk(256);
    const dim3 gFull((NNODES + 127) / 128, 12);   // (79, 12) full
    const dim3 gH0(HN / 128, 12);                 // (40, 12)
    const dim3 gH1((NNODES - HN + 127) / 128, 12);// (39, 12)
    const dim3 gWc12(4, 4, 2);
    const int  aH0 = HN / 8;                      // 640
    const int  aH1 = (NNODES - HN) / 8;           // 610

    cudaStream_t side;
    cudaEvent_t  evFork1, evFork2, evG1, evJoin1, evJoin2;
    cudaEvent_t  eM2, eS2, eM3, eS3, evFinal;
    cudaStreamCreateWithFlags(&side, cudaStreamNonBlocking);
    cudaEventCreateWithFlags(&evFork1, cudaEventDisableTiming);
    cudaEventCreateWithFlags(&evFork2, cudaEventDisableTiming);
    cudaEventCreateWithFlags(&evG1,    cudaEventDisableTiming);
    cudaEventCreateWithFlags(&evJoin1, cudaEventDisableTiming);
    cudaEventCreateWithFlags(&evJoin2, cudaEventDisableTiming);
    cudaEventCreateWithFlags(&eM2, cudaEventDisableTiming);
    cudaEventCreateWithFlags(&eS2, cudaEventDisableTiming);
    cudaEventCreateWithFlags(&eM3, cudaEventDisableTiming);
    cudaEventCreateWithFlags(&eS3, cudaEventDisableTiming);
    cudaEventCreateWithFlags(&evFinal, cudaEventDisableTiming);

    // ---- fork: CSR chain + wc12 on side, cvt/gemm on main ----
    cudaEventRecord(evFork1, 0);
    cudaStreamWaitEvent(side, evFork1, 0);
    hist_kernel<<<(NEDGES + 255) / 256, blk, 0, side>>>(ei);
    scan_kernel<<<1, 1024, 0, side>>>();
    scatter_kernel<<<(NEDGES + 255) / 256, blk, 0, side>>>(ei);
    cudaEventRecord(evJoin1, side);

    cvt_all<<<(E_B2 + 255) / 256, blk>>>(x, W_lin[0], W_lin[1], W_lin[2],
                                         W_s1[0], W_s1[1], W_s1[2],
                                         b_lin[0], b_lin[1], b_lin[2],
                                         b_s1[0], b_s1[1], b_s1[2]);
    cudaEventRecord(evFork2, 0);
    cudaStreamWaitEvent(side, evFork2, 0);
    wc_gemm12<<<gWc12, blk, 0, side>>>();
    cudaEventRecord(evJoin2, side);

    // main: Wc[0] + full layer-1 GEMM -> buf0
    wc_gemm0<<<4, blk>>>();
    layer_gemm<<<gFull, blk>>>(xhi, xlo, 0, 64, Hb[0], ABb[0], 0);
    cudaEventRecord(evG1, 0);

    // ---- layer 1 agg (split) ----
    cudaStreamWaitEvent(0, evJoin1, 0);            // CSR for h0
    agg_kernel<0><<<aH0, blk>>>(ABb[0], Hb[0], W_s2[0], b_s2[0], nullptr, Ahi, Alo, 0);

    cudaStreamWaitEvent(side, evG1, 0);            // gemm1 done (CSR in-order on side)
    agg_kernel<0><<<aH1, blk, 0, side>>>(ABb[0], Hb[0], W_s2[0], b_s2[0], nullptr, Ahi, Alo, HN);

    // ---- layer 2 GEMM (split, ping-pong -> buf1); overlaps opposite agg half ----
    cudaStreamWaitEvent(0, evJoin2, 0);            // Wc[1] ready
    layer_gemm<<<gH0, blk>>>(Ahi, Alo, 1, 256, Hb[1], ABb[1], 0);
    cudaEventRecord(eM2, 0);
    layer_gemm<<<gH1, blk, 0, side>>>(Ahi, Alo, 1, 256, Hb[1], ABb[1], HN);
    cudaEventRecord(eS2, side);

    // ---- layer 2 agg (each half needs BOTH gemm halves) ----
    cudaStreamWaitEvent(0, eS2, 0);
    agg_kernel<0><<<aH0, blk>>>(ABb[1], Hb[1], W_s2[1], b_s2[1], nullptr, Ahi, Alo, 0);
    cudaStreamWaitEvent(side, eM2, 0);
    agg_kernel<0><<<aH1, blk, 0, side>>>(ABb[1], Hb[1], W_s2[1], b_s2[1], nullptr, Ahi, Alo, HN);

    // ---- layer 3 GEMM (split -> buf0) ----
    layer_gemm<<<gH0, blk>>>(Ahi, Alo, 2, 256, Hb[0], ABb[0], 0);
    cudaEventRecord(eM3, 0);
    layer_gemm<<<gH1, blk, 0, side>>>(Ahi, Alo, 2, 256, Hb[0], ABb[0], HN);
    cudaEventRecord(eS3, side);

    // ---- layer 3 agg (writes d_out) ----
    cudaStreamWaitEvent(0, eS3, 0);
    agg_kernel<1><<<aH0, blk>>>(ABb[0], Hb[0], W_s2[2], b_s2[2], out, nullptr, nullptr, 0);
    cudaStreamWaitEvent(side, eM3, 0);
    agg_kernel<1><<<aH1, blk, 0, side>>>(ABb[0], Hb[0], W_s2[2], b_s2[2], out, nullptr, nullptr, HN);
    cudaEventRecord(evFinal, side);
    cudaStreamWaitEvent(0, evFinal, 0);
}